// round 10
// baseline (speedup 1.0000x reference)
#include <cuda_runtime.h>
#include <cuda_bf16.h>
#include <math.h>

#define B_ 2
#define C_ 256
#define N_ 4096
#define D_ 64
#define K_ 32
#define M_ 256
#define R_ 416
#define RP2 512
#define INVSCALE (1.0f/8.000001f)
typedef unsigned long long ull;
typedef unsigned int uint;

// ----------------------------- scratch -----------------------------
__device__ __align__(16) __nv_bfloat16 g_Wh[RP2*C_];
__device__ __align__(16) __nv_bfloat16 g_Wl[RP2*C_];
__device__ __align__(16) __nv_bfloat16 g_xh[B_*C_*N_];
__device__ __align__(16) __nv_bfloat16 g_xl[B_*C_*N_];
__device__ float g_bias[R_];
__device__ float g_P[B_*R_*N_];        // [sem(32); q(64); k(64); fv(256)] x N
__device__ float g_sem[B_*K_*N_];
__device__ int   g_ti[B_*K_*M_];
__device__ int   g_cnt[B_*K_];
__device__ int   g_plist[B_*K_*N_];
__device__ float g_qT[B_*N_*D_];
__device__ float g_kT[B_*N_*D_];
__device__ float g_fvT[B_*N_*C_];
__device__ float g_xT[B_*N_*C_];
__device__ float g_RK[B_*K_*D_];
__device__ float g_RFV[B_*K_*C_];
__device__ float g_outT[B_*N_*C_];

__device__ __forceinline__ void split_bf16(float v, __nv_bfloat16& h, __nv_bfloat16& l) {
    h = __float2bfloat16_rn(v);
    l = __float2bfloat16_rn(v - __bfloat162float(h));
}
__device__ __forceinline__ uint cvta_smem(const void* p) {
    return (uint)__cvta_generic_to_shared(p);
}

// ----------------------------- k_zero -----------------------------
__global__ void k_zero() {
    int w = blockIdx.x*256 + threadIdx.x;       // 48*256 = 12288
    ((uint*)g_Wh)[53248 + w] = 0;
    ((uint*)g_Wl)[53248 + w] = 0;
    if (w < 4096) ((float*)g_RK)[w] = 0.f;
    if (w < 8192) { g_RFV[w] = 0.f; g_RFV[w + 8192] = 0.f; }
    if (blockIdx.x == 0 && threadIdx.x < B_*K_) g_cnt[threadIdx.x] = 0;
}

// ----------------------------- k_cvtx -----------------------------
__global__ void __launch_bounds__(256) k_cvtx(const float* __restrict__ x) {
    __shared__ float t[64][33];
    int b = blockIdx.z, n0 = blockIdx.x*64, c0 = blockIdx.y*32;
    int tx = threadIdx.x, ty = threadIdx.y;
    #pragma unroll
    for (int i = 0; i < 4; i++) {
        int c = c0 + ty + i*8;
        int n = n0 + tx*2;
        float2 v = *(const float2*)&x[(b*C_ + c)*N_ + n];
        __nv_bfloat16 h0, l0, h1, l1;
        split_bf16(v.x, h0, l0); split_bf16(v.y, h1, l1);
        uint hw = (uint)__bfloat16_as_ushort(h0) | ((uint)__bfloat16_as_ushort(h1) << 16);
        uint lw = (uint)__bfloat16_as_ushort(l0) | ((uint)__bfloat16_as_ushort(l1) << 16);
        *(uint*)&g_xh[(b*C_ + c)*N_ + n] = hw;
        *(uint*)&g_xl[(b*C_ + c)*N_ + n] = lw;
        t[tx*2][ty + i*8]     = v.x;
        t[tx*2 + 1][ty + i*8] = v.y;
    }
    __syncthreads();
    #pragma unroll
    for (int i = 0; i < 8; i++) {
        int nn = ty + i*8;
        g_xT[(b*N_ + n0 + nn)*C_ + c0 + tx] = t[nn][tx];
    }
}

// ----------------------------- k_prep -----------------------------
__global__ void __launch_bounds__(256) k_prep(
    const float* __restrict__ sem_w, const float* __restrict__ sem_b,
    const float* __restrict__ q_w,  const float* __restrict__ k_w,
    const float* __restrict__ v_w,  const float* __restrict__ fuse_w) {
    int blk = blockIdx.x, tid = threadIdx.x;
    if (blk < 10) {
        #pragma unroll
        for (int it = 0; it < 16; it++) {
            int e = tid + it*256;
            int r = blk*16 + (e >> 8), c = e & 255;
            float val = (r < 32) ? sem_w[r*C_ + c]
                      : (r < 96) ? q_w[(r-32)*C_ + c]
                                 : k_w[(r-96)*C_ + c];
            __nv_bfloat16 h, l; split_bf16(val, h, l);
            g_Wh[r*C_ + c] = h; g_Wl[r*C_ + c] = l;
            if (c == 0) g_bias[r] = (r < 32) ? sem_b[r] : 0.f;
        }
    } else {
        int r0 = 160 + (blk-10)*8;
        __shared__ float fw[8*256];
        #pragma unroll
        for (int it = 0; it < 8; it++) {
            int e = tid + it*256;
            fw[e] = fuse_w[(r0-160)*C_ + e];
        }
        __syncthreads();
        float acc[8] = {};
        for (int m = 0; m < C_; m++) {
            float v = v_w[m*C_ + tid];
            #pragma unroll
            for (int rr = 0; rr < 8; rr++) acc[rr] += fw[rr*256 + m] * v;
        }
        #pragma unroll
        for (int rr = 0; rr < 8; rr++) {
            int r = r0 + rr;
            __nv_bfloat16 h, l; split_bf16(acc[rr], h, l);
            g_Wh[r*C_ + tid] = h; g_Wl[r*C_ + tid] = l;
            if (tid == 0) g_bias[r] = 0.f;
        }
    }
}

// ----------------------------- k_gemm (128x256 tile, 3-stage cp.async, 1 CTA/SM) ---
__device__ __forceinline__ void mma16816(float* d, const uint* a, uint b0, uint b1) {
    asm volatile(
        "mma.sync.aligned.m16n8k16.row.col.f32.bf16.bf16.f32 "
        "{%0,%1,%2,%3}, {%4,%5,%6,%7}, {%8,%9}, {%0,%1,%2,%3};"
        : "+f"(d[0]), "+f"(d[1]), "+f"(d[2]), "+f"(d[3])
        : "r"(a[0]), "r"(a[1]), "r"(a[2]), "r"(a[3]), "r"(b0), "r"(b1));
}
__device__ __forceinline__ void ldsm4(uint* r, uint addr) {
    asm volatile("ldmatrix.sync.aligned.m8n8.x4.shared.b16 {%0,%1,%2,%3}, [%4];"
        : "=r"(r[0]), "=r"(r[1]), "=r"(r[2]), "=r"(r[3]) : "r"(addr));
}
__device__ __forceinline__ void ldsm4t(uint* r, uint addr) {
    asm volatile("ldmatrix.sync.aligned.m8n8.x4.trans.shared.b16 {%0,%1,%2,%3}, [%4];"
        : "=r"(r[0]), "=r"(r[1]), "=r"(r[2]), "=r"(r[3]) : "r"(addr));
}
__device__ __forceinline__ void cpa16(uint dst, const void* src) {
    asm volatile("cp.async.cg.shared.global [%0], [%1], 16;" :: "r"(dst), "l"(src));
}

#define BN_ 256
#define A_ST_BYTES (128*40*2)          // 10240
#define B_ST_BYTES (32*264*2)          // 16896
#define SB_BASE_OFF (6*A_ST_BYTES)     // 61440
#define GEMM_SMEM (6*A_ST_BYTES + 6*B_ST_BYTES)   // 162816 -> forces 1 CTA/SM

__device__ __forceinline__ void gemm_load(int st, int kc, int r0, int n0,
                                          const __nv_bfloat16* xh, const __nv_bfloat16* xl,
                                          uint sa_base, uint sb_base, int tid) {
    #pragma unroll
    for (int i = 0; i < 4; i++) {
        int ch = tid + i*256;
        int hl = ch >> 9, rem = ch & 511;
        int r = rem >> 2, c = (rem & 3)*8;
        const __nv_bfloat16* src = (hl ? g_Wl : g_Wh) + (r0 + r)*C_ + kc + c;
        cpa16(sa_base + (st*2 + hl)*A_ST_BYTES + (r*40 + c)*2, src);
    }
    #pragma unroll
    for (int i = 0; i < 8; i++) {
        int ch = tid + i*256;
        int hl = ch >> 10, rem = ch & 1023;
        int k = rem >> 5, c = (rem & 31)*8;
        const __nv_bfloat16* src = (hl ? xl : xh) + (kc + k)*N_ + n0 + c;
        cpa16(sb_base + (st*2 + hl)*B_ST_BYTES + (k*264 + c)*2, src);
    }
    asm volatile("cp.async.commit_group;" ::: "memory");
}

__global__ void __launch_bounds__(256, 1) k_gemm() {
    extern __shared__ __align__(16) char dsm[];
    uint sa_base = cvta_smem(dsm);
    uint sb_base = sa_base + SB_BASE_OFF;

    int n0 = blockIdx.x*BN_, r0 = blockIdx.y*128, b = blockIdx.z;
    int tid = threadIdx.x, lane = tid & 31, wid = tid >> 5;
    int wm = wid & 3, wn = wid >> 2;
    const __nv_bfloat16* xh = g_xh + b*C_*N_;
    const __nv_bfloat16* xl = g_xl + b*C_*N_;

    float acc[2][16][4];
    #pragma unroll
    for (int mt = 0; mt < 2; mt++)
        #pragma unroll
        for (int nt = 0; nt < 16; nt++)
            #pragma unroll
            for (int i = 0; i < 4; i++) acc[mt][nt][i] = 0.f;

    gemm_load(0, 0,  r0, n0, xh, xl, sa_base, sb_base, tid);
    gemm_load(1, 32, r0, n0, xh, xl, sa_base, sb_base, tid);

    for (int kt = 0; kt < 8; kt++) {
        if (kt < 7) asm volatile("cp.async.wait_group 1;" ::: "memory");
        else        asm volatile("cp.async.wait_group 0;" ::: "memory");
        __syncthreads();
        int st = kt % 3;
        uint sa0 = sa_base + (st*2+0)*A_ST_BYTES;
        uint sa1 = sa_base + (st*2+1)*A_ST_BYTES;
        uint sb0 = sb_base + (st*2+0)*B_ST_BYTES;
        uint sb1 = sb_base + (st*2+1)*B_ST_BYTES;
        #pragma unroll
        for (int k16 = 0; k16 < 2; k16++) {
            uint ah0[4], ah1[4], al0[4], al1[4];
            int ra = wm*32 + (lane & 15);
            int kcol = k16*16 + (lane >> 4)*8;
            ldsm4(ah0, sa0 + (ra*40 + kcol)*2);
            ldsm4(ah1, sa0 + ((ra+16)*40 + kcol)*2);
            ldsm4(al0, sa1 + (ra*40 + kcol)*2);
            ldsm4(al1, sa1 + ((ra+16)*40 + kcol)*2);
            int krow = k16*16 + (lane & 15);
            #pragma unroll
            for (int np = 0; np < 8; np++) {
                int nc = wn*128 + np*16 + (lane >> 4)*8;
                uint bh[4], bl[4];
                ldsm4t(bh, sb0 + (krow*264 + nc)*2);
                ldsm4t(bl, sb1 + (krow*264 + nc)*2);
                mma16816(acc[0][np*2],   ah0, bh[0], bh[1]);
                mma16816(acc[1][np*2],   ah1, bh[0], bh[1]);
                mma16816(acc[0][np*2+1], ah0, bh[2], bh[3]);
                mma16816(acc[1][np*2+1], ah1, bh[2], bh[3]);
                mma16816(acc[0][np*2],   ah0, bl[0], bl[1]);
                mma16816(acc[1][np*2],   ah1, bl[0], bl[1]);
                mma16816(acc[0][np*2+1], ah0, bl[2], bl[3]);
                mma16816(acc[1][np*2+1], ah1, bl[2], bl[3]);
                mma16816(acc[0][np*2],   al0, bh[0], bh[1]);
                mma16816(acc[1][np*2],   al1, bh[0], bh[1]);
                mma16816(acc[0][np*2+1], al0, bh[2], bh[3]);
                mma16816(acc[1][np*2+1], al1, bh[2], bh[3]);
            }
        }
        __syncthreads();
        if (kt + 2 < 8)
            gemm_load((kt+2) % 3, (kt+2)*32, r0, n0, xh, xl, sa_base, sb_base, tid);
    }

    // ---- epilogue: bias, direct P write, SMEM transpose for qT/kT/fvT ----
    float* T = (float*)dsm;                 // 128 x 261 floats (133632 B <= GEMM_SMEM)
    #pragma unroll
    for (int mt = 0; mt < 2; mt++) {
        int rl = wm*32 + mt*16 + (lane >> 2);
        int r = r0 + rl;
        float bi0 = (r < R_) ? g_bias[r] : 0.f;
        float bi1 = (r + 8 < R_) ? g_bias[r + 8] : 0.f;
        #pragma unroll
        for (int nt = 0; nt < 16; nt++) {
            int nl = wn*128 + nt*8 + (lane & 3)*2;
            float v0 = acc[mt][nt][0] + bi0, v1 = acc[mt][nt][1] + bi0;
            float v2 = acc[mt][nt][2] + bi1, v3 = acc[mt][nt][3] + bi1;
            T[rl*261 + nl] = v0; T[rl*261 + nl + 1] = v1;
            T[(rl+8)*261 + nl] = v2; T[(rl+8)*261 + nl + 1] = v3;
            if (r < R_ && !(r >= 32 && r < 96))
                *(float2*)&g_P[(b*R_ + r)*N_ + n0 + nl] = make_float2(v0, v1);
            if (r + 8 < R_ && !(r + 8 >= 32 && r + 8 < 96))
                *(float2*)&g_P[(b*R_ + r + 8)*N_ + n0 + nl] = make_float2(v2, v3);
        }
    }
    __syncthreads();
    for (int i = 0; i < 128; i++) {
        int e = tid + i*256;
        int rl = e & 127, nl = e >> 7;
        int r = r0 + rl;
        if (r >= 32 && r < R_) {
            float v = T[rl*261 + nl];
            int n = n0 + nl;
            if (r < 96)       g_qT[(b*N_ + n)*D_ + (r - 32)]  = v;
            else if (r < 160) g_kT[(b*N_ + n)*D_ + (r - 96)]  = v;
            else              g_fvT[(b*N_ + n)*C_ + (r - 160)] = v;
        }
    }
}

// ----------------------------- k_sem -----------------------------
__global__ void __launch_bounds__(256) k_sem() {
    int g = blockIdx.x*256 + threadIdx.x;
    int pos = g >> 2, s = g & 3;
    int b = pos >> 12, n = pos & (N_-1);
    float l[8];
    float mx = -INFINITY; int am = K_;
    #pragma unroll
    for (int j = 0; j < 8; j++) {
        l[j] = g_P[(b*R_ + s*8 + j)*N_ + n];
        if (l[j] > mx) { mx = l[j]; am = s*8 + j; }
    }
    #pragma unroll
    for (int off = 1; off <= 2; off <<= 1) {
        float ov = __shfl_xor_sync(0xFFFFFFFFu, mx, off);
        int   oa = __shfl_xor_sync(0xFFFFFFFFu, am, off);
        if (ov > mx || (ov == mx && oa < am)) { mx = ov; am = oa; }
    }
    float sum = 0.f;
    #pragma unroll
    for (int j = 0; j < 8; j++) { l[j] = expf(l[j] - mx); sum += l[j]; }
    #pragma unroll
    for (int off = 1; off <= 2; off <<= 1)
        sum += __shfl_xor_sync(0xFFFFFFFFu, sum, off);
    float inv = 1.f/sum;
    #pragma unroll
    for (int j = 0; j < 8; j++) g_sem[(b*K_ + s*8 + j)*N_ + n] = l[j]*inv;
    if (s == 0) {
        int slot = atomicAdd(&g_cnt[b*K_ + am], 1);
        g_plist[(b*K_+am)*N_ + slot] = n;
    }
}

// ----------------------------- k_sel -----------------------------
__global__ void __launch_bounds__(512) k_sel() {
    __shared__ ull cand[4096];
    __shared__ ull win[256];
    __shared__ int sufc[256];
    __shared__ int s_tc, s_cA, s_t, s_A, s_nw, s_nc;
    unsigned* hist = (unsigned*)cand;

    int bk = blockIdx.x; int b = bk >> 5, k = bk & 31;
    int tid = threadIdx.x;
    const float* row = g_sem + (b*K_ + k)*N_;

    for (int i = tid; i < 4096; i += 512) hist[i] = 0;
    __syncthreads();

    unsigned vb[8];
    #pragma unroll
    for (int j = 0; j < 8; j++) {
        vb[j] = __float_as_uint(row[tid + j*512]);
        atomicAdd(&hist[vb[j] >> 20], 1);
    }
    __syncthreads();

    if (tid < 256) {
        int cs = 0;
        #pragma unroll
        for (int h = 0; h < 16; h++) cs += hist[tid*16 + h];
        sufc[tid] = cs;
    }
    __syncthreads();
    #pragma unroll
    for (int st = 1; st < 256; st <<= 1) {
        int add = (tid < 256 && tid + st < 256) ? sufc[tid + st] : 0;
        __syncthreads();
        if (tid < 256) sufc[tid] += add;
        __syncthreads();
    }
    if (tid < 256) {
        int nxt = (tid < 255) ? sufc[tid + 1] : 0;
        if (sufc[tid] >= M_ && nxt < M_) { s_tc = tid; s_cA = nxt; }
    }
    if (tid == 0) { s_nw = 0; s_nc = 0; }
    __syncthreads();
    int tc = s_tc, cA = s_cA;
    if (tid < 16) {
        int sg = 0;
        for (int j = tid; j < 16; j++) sg += hist[tc*16 + j];
        int hi = hist[tc*16 + tid];
        if (cA + sg >= M_ && cA + sg - hi < M_) { s_t = tc*16 + tid; s_A = cA + sg - hi; }
    }
    __syncthreads();
    int t = s_t, A = s_A, s = M_ - A;
    __syncthreads();

    #pragma unroll
    for (int j = 0; j < 8; j++) {
        unsigned v = vb[j];
        int idx = tid + j*512;
        unsigned bkt = v >> 20;
        ull key = ((ull)v << 32) | (unsigned)(0xFFFFFFFFu - (unsigned)idx);
        if ((int)bkt > t) { int p = atomicAdd(&s_nw, 1); win[p] = ~key; }
        else if ((int)bkt == t) { int p = atomicAdd(&s_nc, 1); cand[p] = ~key; }
    }
    __syncthreads();

    int nc = s_nc;
    int P = 1; while (P < nc) P <<= 1;
    for (int i = tid; i < P; i += 512) if (i >= nc) cand[i] = 0xFFFFFFFFFFFFFFFFULL;
    __syncthreads();
    for (int sz = 2; sz <= P; sz <<= 1) {
        for (int str = sz >> 1; str > 0; str >>= 1) {
            for (int i = tid; i < P; i += 512) {
                int l = i ^ str;
                if (l > i) {
                    ull a = cand[i], c2 = cand[l];
                    bool up = ((i & sz) == 0);
                    if ((a > c2) == up) { cand[i] = c2; cand[l] = a; }
                }
            }
            __syncthreads();
        }
    }
    for (int i = tid; i < s; i += 512) win[A + i] = cand[i];
    __syncthreads();
    for (int sz = 2; sz <= 256; sz <<= 1) {
        for (int str = sz >> 1; str > 0; str >>= 1) {
            if (tid < 256) {
                int i = tid, l = i ^ str;
                if (l > i) {
                    ull a = win[i], c2 = win[l];
                    bool up = ((i & sz) == 0);
                    if ((a > c2) == up) { win[i] = c2; win[l] = a; }
                }
            }
            __syncthreads();
        }
    }
    if (tid < 256) g_ti[(b*K_ + k)*M_ + tid] = (int)(unsigned)(win[tid] & 0xFFFFFFFFu);
}

// ----------------------------- k_transpO -----------------------------
__global__ void k_transpO(float* __restrict__ out) {
    __shared__ float t[32][33];
    int b = blockIdx.z, c0 = blockIdx.x*32, n0 = blockIdx.y*32;
    int tx = threadIdx.x, ty = threadIdx.y;
    #pragma unroll
    for (int i = 0; i < 32; i += 8)
        t[ty+i][tx] = g_outT[b*N_*C_ + (n0 + ty + i)*C_ + c0 + tx];
    __syncthreads();
    #pragma unroll
    for (int i = 0; i < 32; i += 8)
        out[b*C_*N_ + (c0 + ty + i)*N_ + n0 + tx] = t[tx][ty+i];
}

// ----------------------------- k_region -----------------------------
__global__ void __launch_bounds__(256) k_region() {
    __shared__ float ss[32*68];
    __shared__ float ps[64*68];
    int ct = blockIdx.x, sp = blockIdx.y, b = blockIdx.z;
    int tid = threadIdx.x;
    int kk = tid & 31, cg = tid >> 5;
    float acc[8] = {};
    for (int nch = 0; nch < 4; nch++) {
        int nn0 = sp*256 + nch*64;
        #pragma unroll
        for (int i = 0; i < 8; i++) {
            int e = tid + i*256; int kr = e >> 6, nn = e & 63;
            ss[kr*68+nn] = g_sem[(b*K_+kr)*N_ + nn0 + nn];
        }
        #pragma unroll
        for (int i = 0; i < 16; i++) {
            int e = tid + i*256; int c = e >> 6, nn = e & 63;
            ps[c*68+nn] = g_P[(b*R_ + 96 + ct*64 + c)*N_ + nn0 + nn];
        }
        __syncthreads();
        #pragma unroll 4
        for (int nn = 0; nn < 64; nn += 4) {
            float4 sv = *(const float4*)&ss[kk*68 + nn];
            #pragma unroll
            for (int j = 0; j < 8; j++) {
                float4 pv = *(const float4*)&ps[(cg*8+j)*68 + nn];
                acc[j] += sv.x*pv.x;
                acc[j] += sv.y*pv.y;
                acc[j] += sv.z*pv.z;
                acc[j] += sv.w*pv.w;
            }
        }
        __syncthreads();
    }
    #pragma unroll
    for (int j = 0; j < 8; j++) {
        int o = ct*64 + cg*8 + j;
        if (o < 64) atomicAdd(&g_RK[(b*K_+kk)*D_ + o], acc[j]);
        else        atomicAdd(&g_RFV[(b*K_+kk)*C_ + (o-64)], acc[j]);
    }
}

// ----------------------------- k_main -----------------------------
#define MCHUNKS 16
__global__ void __launch_bounds__(256) k_main(const float* __restrict__ alpha_p,
                                              const float* __restrict__ fuse_b,
                                              const float* __restrict__ ln_g,
                                              const float* __restrict__ ln_b) {
    extern __shared__ float sm[];
    float* s_pkT = sm;                         // 64*257
    float* s_rfv = s_pkT + 64*257;             // 32*256
    float* s_rk  = s_rfv + 32*256;             // 32*65
    int*   s_pool= (int*)(s_rk + 32*65);       // 256

    int reg = blockIdx.y, b = blockIdx.z;
    int cnt = g_cnt[b*K_ + reg];
    if ((int)blockIdx.x * 64 >= cnt) return;
    int tid = threadIdx.x, lane = tid & 31, w = tid >> 5;

    if (tid < M_) s_pool[tid] = g_ti[(b*K_+reg)*M_ + tid];
    __syncthreads();
    #pragma unroll 4
    for (int i = 0; i < 64; i++) {
        int e = tid + i*256;
        int m = e >> 6, d = e & 63;
        s_pkT[d*257 + m] = g_kT[(b*N_ + s_pool[m])*D_ + d];
    }
    #pragma unroll
    for (int i = 0; i < 32; i++) s_rfv[tid + i*256] = g_RFV[b*K_*C_ + tid + i*256];
    #pragma unroll
    for (int i = 0; i < 8; i++) {
        int e = tid + i*256; int kk = e >> 6, d = e & 63;
        s_rk[kk*65+d] = g_RK[(b*K_+kk)*D_ + d];
    }
    __syncthreads();

    float a = 1.f/(1.f + expf(-alpha_p[0]));

    for (int chunk = blockIdx.x; chunk*64 < cnt; chunk += MCHUNKS) {
        int base = chunk*64;
        int pend = min(base+64, cnt);
        for (int g = 0; g < 2; g++) {
            int p0 = base + w*8 + g*4;
            if (p0 >= pend) break;
            int nv = min(4, pend - p0);
            int n[4]; float q0[4], q1[4];
            #pragma unroll
            for (int i = 0; i < 4; i++) {
                if (i < nv) {
                    n[i] = g_plist[(b*K_+reg)*N_ + p0 + i];
                    q0[i] = g_qT[(b*N_+n[i])*D_ + lane];
                    q1[i] = g_qT[(b*N_+n[i])*D_ + 32 + lane];
                } else { n[i] = 0; q0[i] = 0.f; q1[i] = 0.f; }
            }

            float sims[4][8] = {};
            #pragma unroll
            for (int dh = 0; dh < 2; dh++) {
                #pragma unroll 2
                for (int dd = 0; dd < 32; dd++) {
                    const float* rowp = s_pkT + (dh*32+dd)*257;
                    float r8[8];
                    #pragma unroll
                    for (int mi = 0; mi < 8; mi++) r8[mi] = rowp[mi*32 + lane];
                    #pragma unroll
                    for (int i = 0; i < 4; i++) {
                        float qd = __shfl_sync(0xFFFFFFFFu, dh ? q1[i] : q0[i], dd);
                        #pragma unroll
                        for (int mi = 0; mi < 8; mi++) sims[i][mi] += qd * r8[mi];
                    }
                }
            }

            #pragma unroll 1
            for (int i = 0; i < 4; i++) {
                if (i >= nv) break;
                float sv[8];
                #pragma unroll
                for (int mi = 0; mi < 8; mi++) sv[mi] = sims[i][mi] * INVSCALE;

                float tv[8]; int tm[8];
                unsigned used = 0;
                #pragma unroll
                for (int t = 0; t < 8; t++) {
                    float bv = -INFINITY; int bm = 1 << 30;
                    #pragma unroll
                    for (int mi = 0; mi < 8; mi++) {
                        if (!(used & (1u << mi))) {
                            float v = sv[mi]; int m = mi*32 + lane;
                            if (v > bv || (v == bv && m < bm)) { bv = v; bm = m; }
                        }
                    }
                    #pragma unroll
                    for (int off = 16; off > 0; off >>= 1) {
                        float ov = __shfl_xor_sync(0xFFFFFFFFu, bv, off);
                        int   om = __shfl_xor_sync(0xFFFFFFFFu, bm, off);
                        if (ov > bv || (ov == bv && om < bm)) { bv = ov; bm = om; }
                    }
                    tv[t] = bv; tm[t] = bm;
                    if ((bm & 31) == lane) used |= 1u << (bm >> 5);
                }
                float ww[8], wsum = 0.f;
                #pragma unroll
                for (int t = 0; t < 8; t++) { ww[t] = expf(tv[t] - tv[0]); wsum += ww[t]; }
                float winv = 1.f/wsum;
                float fs[8] = {};
                #pragma unroll
                for (int t = 0; t < 8; t++) {
                    float att = ww[t]*winv;
                    int gidx = s_pool[tm[t]];
                    const float* fvrow = g_fvT + (b*N_ + gidx)*C_;
                    #pragma unroll
                    for (int j = 0; j < 8; j++) fs[j] += att * fvrow[j*32 + lane];
                }
                float lg = 0.f;
                #pragma unroll
                for (int dh = 0; dh < 2; dh++) {
                    #pragma unroll 4
                    for (int dd = 0; dd < 32; dd++) {
                        float qd = __shfl_sync(0xFFFFFFFFu, dh ? q1[i] : q0[i], dd);
                        lg += qd * s_rk[lane*65 + dh*32 + dd];
                    }
                }
                lg *= INVSCALE;
                float mx = lg;
                #pragma unroll
                for (int off = 16; off > 0; off >>= 1)
                    mx = fmaxf(mx, __shfl_xor_sync(0xFFFFFFFFu, mx, off));
                float ev = expf(lg - mx), es = ev;
                #pragma unroll
                for (int off = 16; off > 0; off >>= 1) es += __shfl_xor_sync(0xFFFFFFFFu, es, off);
                float attn = ev/es;
                float fc[8] = {};
                #pragma unroll 4
                for (int kk = 0; kk < K_; kk++) {
                    float ak = __shfl_sync(0xFFFFFFFFu, attn, kk);
                    const float* rrow = s_rfv + kk*256;
                    #pragma unroll
                    for (int j = 0; j < 8; j++) fc[j] += ak * rrow[j*32 + lane];
                }
                float pre[8], sum = 0.f, sq = 0.f;
                const float* xrow = g_xT + (b*N_+n[i])*C_;
                #pragma unroll
                for (int j = 0; j < 8; j++) {
                    int c = j*32 + lane;
                    float f = a*fc[j] + (1.f - a)*fs[j] + fuse_b[c];
                    float v = xrow[c] + f;
                    pre[j] = v; sum += v; sq += v*v;
                }
                #pragma unroll
                for (int off = 16; off > 0; off >>= 1) {
                    sum += __shfl_xor_sync(0xFFFFFFFFu, sum, off);
                    sq  += __shfl_xor_sync(0xFFFFFFFFu, sq,  off);
                }
                float mu = sum * (1.f/256.f);
                float var = sq * (1.f/256.f) - mu*mu;
                float rstd = rsqrtf(var + 1e-5f);
                float* orow = g_outT + (b*N_+n[i])*C_;
                #pragma unroll
                for (int j = 0; j < 8; j++) {
                    int c = j*32 + lane;
                    orow[c] = (pre[j]-mu)*rstd*ln_g[c] + ln_b[c];
                }
            }
        }
    }
}

// ----------------------------- launch -----------------------------
extern "C" void kernel_launch(void* const* d_in, const int* in_sizes, int n_in,
                              void* d_out, int out_size) {
    const float* x      = (const float*)d_in[0];
    const float* sem_w  = (const float*)d_in[1];
    const float* sem_b  = (const float*)d_in[2];
    const float* q_w    = (const float*)d_in[3];
    const float* k_w    = (const float*)d_in[4];
    const float* v_w    = (const float*)d_in[5];
    const float* fuse_w = (const float*)d_in[6];
    const float* fuse_b = (const float*)d_in[7];
    const float* alpha  = (const float*)d_in[8];
    const float* ln_g   = (const float*)d_in[9];
    const float* ln_b   = (const float*)d_in[10];
    float* out = (float*)d_out;

    const int SMEM_MAIN = (64*257 + 32*256 + 32*65)*4 + 256*4;
    cudaFuncSetAttribute((const void*)k_main,
                         cudaFuncAttributeMaxDynamicSharedMemorySize, SMEM_MAIN);
    cudaFuncSetAttribute((const void*)k_gemm,
                         cudaFuncAttributeMaxDynamicSharedMemorySize, GEMM_SMEM);

    k_zero<<<48, 256>>>();                                     // #1
    k_cvtx<<<dim3(64, 8, B_), dim3(32, 8)>>>(x);               // #2
    k_prep<<<42, 256>>>(sem_w, sem_b, q_w, k_w, v_w, fuse_w);  // #3
    k_gemm<<<dim3(16, 4, B_), 256, GEMM_SMEM>>>();             // #4  <- ncu slot
    k_sem<<<128, 256>>>();                                     // #5
    k_sel<<<B_*K_, 512>>>();                                   // #6
    k_region<<<dim3(5, 16, B_), 256>>>();                      // #7
    k_main<<<dim3(MCHUNKS, K_, B_), 256, SMEM_MAIN>>>(alpha, fuse_b, ln_g, ln_b); // #8
    k_transpO<<<dim3(8, 128, B_), dim3(32, 8)>>>(out);         // #9
}

// round 12
// speedup vs baseline: 1.0228x; 1.0228x over previous
#include <cuda_runtime.h>
#include <cuda_bf16.h>
#include <math.h>

#define B_ 2
#define C_ 256
#define N_ 4096
#define D_ 64
#define K_ 32
#define M_ 256
#define R_ 416
#define RP2 512
#define INVSCALE (1.0f/8.000001f)
typedef unsigned long long ull;
typedef unsigned int uint;

// ----------------------------- scratch -----------------------------
__device__ __align__(16) __nv_bfloat16 g_Wh[RP2*C_];
__device__ __align__(16) __nv_bfloat16 g_Wl[RP2*C_];
__device__ __align__(16) __nv_bfloat16 g_xh[B_*C_*N_];
__device__ __align__(16) __nv_bfloat16 g_xl[B_*C_*N_];
__device__ float g_bias[R_];
__device__ float g_P[B_*R_*N_];        // [sem(32); q(64); k(64); fv(256)] x N
__device__ float g_sem[B_*K_*N_];
__device__ int   g_ti[B_*K_*M_];
__device__ int   g_cnt[B_*K_];
__device__ int   g_plist[B_*K_*N_];
__device__ float g_qT[B_*N_*D_];
__device__ float g_kT[B_*N_*D_];
__device__ float g_fvT[B_*N_*C_];
__device__ float g_xT[B_*N_*C_];
__device__ float g_RK[B_*K_*D_];
__device__ float g_RFV[B_*K_*C_];
__device__ float g_outT[B_*N_*C_];

__device__ __forceinline__ void split_bf16(float v, __nv_bfloat16& h, __nv_bfloat16& l) {
    h = __float2bfloat16_rn(v);
    l = __float2bfloat16_rn(v - __bfloat162float(h));
}
__device__ __forceinline__ uint cvta_smem(const void* p) {
    return (uint)__cvta_generic_to_shared(p);
}

// ----------------------------- k_pre (fused zero + cvtx + prep) -----------------------------
// blocks [0,1024): cvtx — x -> bf16 hi/lo + xT
// blocks [1024,1066): prep — build W rows
// blocks [1066,1114): zero — W pad rows, RK/RFV accumulators, counters
__global__ void __launch_bounds__(256) k_pre(
    const float* __restrict__ x,
    const float* __restrict__ sem_w, const float* __restrict__ sem_b,
    const float* __restrict__ q_w,  const float* __restrict__ k_w,
    const float* __restrict__ v_w,  const float* __restrict__ fuse_w) {
    int bx = blockIdx.x, tid = threadIdx.x;
    if (bx < 1024) {
        __shared__ float t[64][33];
        int n0 = (bx & 63)*64, c0 = ((bx >> 6) & 7)*32, b = bx >> 9;
        int tx = tid & 31, ty = tid >> 5;
        #pragma unroll
        for (int i = 0; i < 4; i++) {
            int c = c0 + ty + i*8;
            int n = n0 + tx*2;
            float2 v = *(const float2*)&x[(b*C_ + c)*N_ + n];
            __nv_bfloat16 h0, l0, h1, l1;
            split_bf16(v.x, h0, l0); split_bf16(v.y, h1, l1);
            uint hw = (uint)__bfloat16_as_ushort(h0) | ((uint)__bfloat16_as_ushort(h1) << 16);
            uint lw = (uint)__bfloat16_as_ushort(l0) | ((uint)__bfloat16_as_ushort(l1) << 16);
            *(uint*)&g_xh[(b*C_ + c)*N_ + n] = hw;
            *(uint*)&g_xl[(b*C_ + c)*N_ + n] = lw;
            t[tx*2][ty + i*8]     = v.x;
            t[tx*2 + 1][ty + i*8] = v.y;
        }
        __syncthreads();
        #pragma unroll
        for (int i = 0; i < 8; i++) {
            int nn = ty + i*8;
            g_xT[(b*N_ + n0 + nn)*C_ + c0 + tx] = t[nn][tx];
        }
    } else if (bx < 1066) {
        int blk = bx - 1024;
        if (blk < 10) {
            #pragma unroll
            for (int it = 0; it < 16; it++) {
                int e = tid + it*256;
                int r = blk*16 + (e >> 8), c = e & 255;
                float val = (r < 32) ? sem_w[r*C_ + c]
                          : (r < 96) ? q_w[(r-32)*C_ + c]
                                     : k_w[(r-96)*C_ + c];
                __nv_bfloat16 h, l; split_bf16(val, h, l);
                g_Wh[r*C_ + c] = h; g_Wl[r*C_ + c] = l;
                if (c == 0) g_bias[r] = (r < 32) ? sem_b[r] : 0.f;
            }
        } else {
            int r0 = 160 + (blk-10)*8;
            __shared__ float fw[8*256];
            #pragma unroll
            for (int it = 0; it < 8; it++) {
                int e = tid + it*256;
                fw[e] = fuse_w[(r0-160)*C_ + e];
            }
            __syncthreads();
            float acc[8] = {};
            for (int m = 0; m < C_; m++) {
                float v = v_w[m*C_ + tid];
                #pragma unroll
                for (int rr = 0; rr < 8; rr++) acc[rr] += fw[rr*256 + m] * v;
            }
            #pragma unroll
            for (int rr = 0; rr < 8; rr++) {
                int r = r0 + rr;
                __nv_bfloat16 h, l; split_bf16(acc[rr], h, l);
                g_Wh[r*C_ + tid] = h; g_Wl[r*C_ + tid] = l;
                if (tid == 0) g_bias[r] = 0.f;
            }
        }
    } else {
        int w = (bx - 1066)*256 + tid;          // 48*256 = 12288
        ((uint*)g_Wh)[53248 + w] = 0;           // W pad rows 416..511
        ((uint*)g_Wl)[53248 + w] = 0;
        if (w < 4096) ((float*)g_RK)[w] = 0.f;
        if (w < 8192) { g_RFV[w] = 0.f; g_RFV[w + 8192] = 0.f; }
        if (w < B_*K_) g_cnt[w] = 0;
    }
}

// ----------------------------- k_gemm (3-stage cp.async + ldmatrix, fused transpose epilogue) ---
__device__ __forceinline__ void mma16816(float* d, const uint* a, uint b0, uint b1) {
    asm volatile(
        "mma.sync.aligned.m16n8k16.row.col.f32.bf16.bf16.f32 "
        "{%0,%1,%2,%3}, {%4,%5,%6,%7}, {%8,%9}, {%0,%1,%2,%3};"
        : "+f"(d[0]), "+f"(d[1]), "+f"(d[2]), "+f"(d[3])
        : "r"(a[0]), "r"(a[1]), "r"(a[2]), "r"(a[3]), "r"(b0), "r"(b1));
}
__device__ __forceinline__ void ldsm4(uint* r, uint addr) {
    asm volatile("ldmatrix.sync.aligned.m8n8.x4.shared.b16 {%0,%1,%2,%3}, [%4];"
        : "=r"(r[0]), "=r"(r[1]), "=r"(r[2]), "=r"(r[3]) : "r"(addr));
}
__device__ __forceinline__ void ldsm4t(uint* r, uint addr) {
    asm volatile("ldmatrix.sync.aligned.m8n8.x4.trans.shared.b16 {%0,%1,%2,%3}, [%4];"
        : "=r"(r[0]), "=r"(r[1]), "=r"(r[2]), "=r"(r[3]) : "r"(addr));
}
__device__ __forceinline__ void cpa16(uint dst, const void* src) {
    asm volatile("cp.async.cg.shared.global [%0], [%1], 16;" :: "r"(dst), "l"(src));
}

#define A_ST_BYTES (128*40*2)
#define B_ST_BYTES (32*136*2)
#define SB_BASE_OFF (6*A_ST_BYTES)
#define GEMM_SMEM (6*A_ST_BYTES + 6*B_ST_BYTES)   // 113664; epilogue T 128*133*4=68096 fits

__device__ __forceinline__ void gemm_load(int st, int kc, int r0, int n0,
                                          const __nv_bfloat16* xh, const __nv_bfloat16* xl,
                                          uint sa_base, uint sb_base, int tid) {
    #pragma unroll
    for (int i = 0; i < 4; i++) {
        int ch = tid + i*256;
        int hl = ch >> 9, rem = ch & 511;
        int r = rem >> 2, c = (rem & 3)*8;
        const __nv_bfloat16* src = (hl ? g_Wl : g_Wh) + (r0 + r)*C_ + kc + c;
        cpa16(sa_base + (st*2 + hl)*A_ST_BYTES + (r*40 + c)*2, src);
    }
    #pragma unroll
    for (int i = 0; i < 4; i++) {
        int ch = tid + i*256;
        int hl = ch >> 9, rem = ch & 511;
        int k = rem >> 4, c = (rem & 15)*8;
        const __nv_bfloat16* src = (hl ? xl : xh) + (kc + k)*N_ + n0 + c;
        cpa16(sb_base + (st*2 + hl)*B_ST_BYTES + (k*136 + c)*2, src);
    }
    asm volatile("cp.async.commit_group;" ::: "memory");
}

__global__ void __launch_bounds__(256) k_gemm() {
    extern __shared__ __align__(16) char dsm[];
    uint sa_base = cvta_smem(dsm);
    uint sb_base = sa_base + SB_BASE_OFF;

    int n0 = blockIdx.x*128, r0 = blockIdx.y*128, b = blockIdx.z;
    int tid = threadIdx.x, lane = tid & 31, wid = tid >> 5;
    int wm = wid & 3, wn = wid >> 2;
    const __nv_bfloat16* xh = g_xh + b*C_*N_;
    const __nv_bfloat16* xl = g_xl + b*C_*N_;

    float acc[2][8][4];
    #pragma unroll
    for (int mt = 0; mt < 2; mt++)
        #pragma unroll
        for (int nt = 0; nt < 8; nt++)
            #pragma unroll
            for (int i = 0; i < 4; i++) acc[mt][nt][i] = 0.f;

    gemm_load(0, 0,  r0, n0, xh, xl, sa_base, sb_base, tid);
    gemm_load(1, 32, r0, n0, xh, xl, sa_base, sb_base, tid);

    for (int kt = 0; kt < 8; kt++) {
        if (kt < 7) asm volatile("cp.async.wait_group 1;" ::: "memory");
        else        asm volatile("cp.async.wait_group 0;" ::: "memory");
        __syncthreads();
        int st = kt % 3;
        uint sa0 = sa_base + (st*2+0)*A_ST_BYTES;
        uint sa1 = sa_base + (st*2+1)*A_ST_BYTES;
        uint sb0 = sb_base + (st*2+0)*B_ST_BYTES;
        uint sb1 = sb_base + (st*2+1)*B_ST_BYTES;
        #pragma unroll
        for (int k16 = 0; k16 < 2; k16++) {
            uint ah0[4], ah1[4], al0[4], al1[4];
            int ra = wm*32 + (lane & 15);
            int kcol = k16*16 + (lane >> 4)*8;
            ldsm4(ah0, sa0 + (ra*40 + kcol)*2);
            ldsm4(ah1, sa0 + ((ra+16)*40 + kcol)*2);
            ldsm4(al0, sa1 + (ra*40 + kcol)*2);
            ldsm4(al1, sa1 + ((ra+16)*40 + kcol)*2);
            int krow = k16*16 + (lane & 15);
            #pragma unroll
            for (int np = 0; np < 4; np++) {
                int nc = wn*64 + np*16 + (lane >> 4)*8;
                uint bh[4], bl[4];
                ldsm4t(bh, sb0 + (krow*136 + nc)*2);
                ldsm4t(bl, sb1 + (krow*136 + nc)*2);
                mma16816(acc[0][np*2],   ah0, bh[0], bh[1]);
                mma16816(acc[1][np*2],   ah1, bh[0], bh[1]);
                mma16816(acc[0][np*2+1], ah0, bh[2], bh[3]);
                mma16816(acc[1][np*2+1], ah1, bh[2], bh[3]);
                mma16816(acc[0][np*2],   ah0, bl[0], bl[1]);
                mma16816(acc[1][np*2],   ah1, bl[0], bl[1]);
                mma16816(acc[0][np*2+1], ah0, bl[2], bl[3]);
                mma16816(acc[1][np*2+1], ah1, bl[2], bl[3]);
                mma16816(acc[0][np*2],   al0, bh[0], bh[1]);
                mma16816(acc[1][np*2],   al1, bh[0], bh[1]);
                mma16816(acc[0][np*2+1], al0, bh[2], bh[3]);
                mma16816(acc[1][np*2+1], al1, bh[2], bh[3]);
            }
        }
        __syncthreads();
        if (kt + 2 < 8)
            gemm_load((kt+2) % 3, (kt+2)*32, r0, n0, xh, xl, sa_base, sb_base, tid);
    }

    // ---- epilogue: bias, direct P write, SMEM transpose for qT/kT/fvT ----
    float* T = (float*)dsm;                 // 128 x 133 floats
    #pragma unroll
    for (int mt = 0; mt < 2; mt++) {
        int rl = wm*32 + mt*16 + (lane >> 2);
        int r = r0 + rl;
        float bi0 = (r < R_) ? g_bias[r] : 0.f;
        float bi1 = (r + 8 < R_) ? g_bias[r + 8] : 0.f;
        #pragma unroll
        for (int nt = 0; nt < 8; nt++) {
            int nl = wn*64 + nt*8 + (lane & 3)*2;
            float v0 = acc[mt][nt][0] + bi0, v1 = acc[mt][nt][1] + bi0;
            float v2 = acc[mt][nt][2] + bi1, v3 = acc[mt][nt][3] + bi1;
            T[rl*133 + nl] = v0; T[rl*133 + nl + 1] = v1;
            T[(rl+8)*133 + nl] = v2; T[(rl+8)*133 + nl + 1] = v3;
            if (r < R_ && !(r >= 32 && r < 96))
                *(float2*)&g_P[(b*R_ + r)*N_ + n0 + nl] = make_float2(v0, v1);
            if (r + 8 < R_ && !(r + 8 >= 32 && r + 8 < 96))
                *(float2*)&g_P[(b*R_ + r + 8)*N_ + n0 + nl] = make_float2(v2, v3);
        }
    }
    __syncthreads();
    for (int i = 0; i < 64; i++) {
        int e = tid + i*256;
        int rl = e & 127, nl = e >> 7;
        int r = r0 + rl;
        if (r >= 32 && r < R_) {
            float v = T[rl*133 + nl];
            int n = n0 + nl;
            if (r < 96)       g_qT[(b*N_ + n)*D_ + (r - 32)]  = v;
            else if (r < 160) g_kT[(b*N_ + n)*D_ + (r - 96)]  = v;
            else              g_fvT[(b*N_ + n)*C_ + (r - 160)] = v;
        }
    }
}

// ----------------------------- k_sem -----------------------------
__global__ void __launch_bounds__(256) k_sem() {
    int g = blockIdx.x*256 + threadIdx.x;
    int pos = g >> 2, s = g & 3;
    int b = pos >> 12, n = pos & (N_-1);
    float l[8];
    float mx = -INFINITY; int am = K_;
    #pragma unroll
    for (int j = 0; j < 8; j++) {
        l[j] = g_P[(b*R_ + s*8 + j)*N_ + n];
        if (l[j] > mx) { mx = l[j]; am = s*8 + j; }
    }
    #pragma unroll
    for (int off = 1; off <= 2; off <<= 1) {
        float ov = __shfl_xor_sync(0xFFFFFFFFu, mx, off);
        int   oa = __shfl_xor_sync(0xFFFFFFFFu, am, off);
        if (ov > mx || (ov == mx && oa < am)) { mx = ov; am = oa; }
    }
    float sum = 0.f;
    #pragma unroll
    for (int j = 0; j < 8; j++) { l[j] = expf(l[j] - mx); sum += l[j]; }
    #pragma unroll
    for (int off = 1; off <= 2; off <<= 1)
        sum += __shfl_xor_sync(0xFFFFFFFFu, sum, off);
    float inv = 1.f/sum;
    #pragma unroll
    for (int j = 0; j < 8; j++) g_sem[(b*K_ + s*8 + j)*N_ + n] = l[j]*inv;
    if (s == 0) {
        int slot = atomicAdd(&g_cnt[b*K_ + am], 1);
        g_plist[(b*K_+am)*N_ + slot] = n;
    }
}

// ----------------------------- k_region -----------------------------
__global__ void __launch_bounds__(256) k_region() {
    __shared__ float ss[32*68];
    __shared__ float ps[64*68];
    int ct = blockIdx.x, sp = blockIdx.y, b = blockIdx.z;
    int tid = threadIdx.x;
    int kk = tid & 31, cg = tid >> 5;
    float acc[8] = {};
    for (int nch = 0; nch < 4; nch++) {
        int nn0 = sp*256 + nch*64;
        #pragma unroll
        for (int i = 0; i < 8; i++) {
            int e = tid + i*256; int kr = e >> 6, nn = e & 63;
            ss[kr*68+nn] = g_sem[(b*K_+kr)*N_ + nn0 + nn];
        }
        #pragma unroll
        for (int i = 0; i < 16; i++) {
            int e = tid + i*256; int c = e >> 6, nn = e & 63;
            ps[c*68+nn] = g_P[(b*R_ + 96 + ct*64 + c)*N_ + nn0 + nn];
        }
        __syncthreads();
        #pragma unroll 4
        for (int nn = 0; nn < 64; nn += 4) {
            float4 sv = *(const float4*)&ss[kk*68 + nn];
            #pragma unroll
            for (int j = 0; j < 8; j++) {
                float4 pv = *(const float4*)&ps[(cg*8+j)*68 + nn];
                acc[j] += sv.x*pv.x;
                acc[j] += sv.y*pv.y;
                acc[j] += sv.z*pv.z;
                acc[j] += sv.w*pv.w;
            }
        }
        __syncthreads();
    }
    #pragma unroll
    for (int j = 0; j < 8; j++) {
        int o = ct*64 + cg*8 + j;
        if (o < 64) atomicAdd(&g_RK[(b*K_+kk)*D_ + o], acc[j]);
        else        atomicAdd(&g_RFV[(b*K_+kk)*C_ + (o-64)], acc[j]);
    }
}

// ----------------------------- k_sel -----------------------------
__global__ void __launch_bounds__(512) k_sel() {
    __shared__ ull cand[4096];
    __shared__ ull win[256];
    __shared__ int sufc[256];
    __shared__ int s_tc, s_cA, s_t, s_A, s_nw, s_nc;
    unsigned* hist = (unsigned*)cand;

    int bk = blockIdx.x; int b = bk >> 5, k = bk & 31;
    int tid = threadIdx.x;
    const float* row = g_sem + (b*K_ + k)*N_;

    for (int i = tid; i < 4096; i += 512) hist[i] = 0;
    __syncthreads();

    unsigned vb[8];
    #pragma unroll
    for (int j = 0; j < 8; j++) {
        vb[j] = __float_as_uint(row[tid + j*512]);
        atomicAdd(&hist[vb[j] >> 20], 1);
    }
    __syncthreads();

    if (tid < 256) {
        int cs = 0;
        #pragma unroll
        for (int h = 0; h < 16; h++) cs += hist[tid*16 + h];
        sufc[tid] = cs;
    }
    __syncthreads();
    #pragma unroll
    for (int st = 1; st < 256; st <<= 1) {
        int add = (tid < 256 && tid + st < 256) ? sufc[tid + st] : 0;
        __syncthreads();
        if (tid < 256) sufc[tid] += add;
        __syncthreads();
    }
    if (tid < 256) {
        int nxt = (tid < 255) ? sufc[tid + 1] : 0;
        if (sufc[tid] >= M_ && nxt < M_) { s_tc = tid; s_cA = nxt; }
    }
    if (tid == 0) { s_nw = 0; s_nc = 0; }
    __syncthreads();
    int tc = s_tc, cA = s_cA;
    if (tid < 16) {
        int sg = 0;
        for (int j = tid; j < 16; j++) sg += hist[tc*16 + j];
        int hi = hist[tc*16 + tid];
        if (cA + sg >= M_ && cA + sg - hi < M_) { s_t = tc*16 + tid; s_A = cA + sg - hi; }
    }
    __syncthreads();
    int t = s_t, A = s_A, s = M_ - A;
    __syncthreads();

    #pragma unroll
    for (int j = 0; j < 8; j++) {
        unsigned v = vb[j];
        int idx = tid + j*512;
        unsigned bkt = v >> 20;
        ull key = ((ull)v << 32) | (unsigned)(0xFFFFFFFFu - (unsigned)idx);
        if ((int)bkt > t) { int p = atomicAdd(&s_nw, 1); win[p] = ~key; }
        else if ((int)bkt == t) { int p = atomicAdd(&s_nc, 1); cand[p] = ~key; }
    }
    __syncthreads();

    int nc = s_nc;
    int P = 1; while (P < nc) P <<= 1;
    for (int i = tid; i < P; i += 512) if (i >= nc) cand[i] = 0xFFFFFFFFFFFFFFFFULL;
    __syncthreads();
    for (int sz = 2; sz <= P; sz <<= 1) {
        for (int str = sz >> 1; str > 0; str >>= 1) {
            for (int i = tid; i < P; i += 512) {
                int l = i ^ str;
                if (l > i) {
                    ull a = cand[i], c2 = cand[l];
                    bool up = ((i & sz) == 0);
                    if ((a > c2) == up) { cand[i] = c2; cand[l] = a; }
                }
            }
            __syncthreads();
        }
    }
    for (int i = tid; i < s; i += 512) win[A + i] = cand[i];
    __syncthreads();
    for (int sz = 2; sz <= 256; sz <<= 1) {
        for (int str = sz >> 1; str > 0; str >>= 1) {
            if (tid < 256) {
                int i = tid, l = i ^ str;
                if (l > i) {
                    ull a = win[i], c2 = win[l];
                    bool up = ((i & sz) == 0);
                    if ((a > c2) == up) { win[i] = c2; win[l] = a; }
                }
            }
            __syncthreads();
        }
    }
    if (tid < 256) g_ti[(b*K_ + k)*M_ + tid] = (int)(unsigned)(win[tid] & 0xFFFFFFFFu);
}

// ----------------------------- k_transpO -----------------------------
__global__ void k_transpO(float* __restrict__ out) {
    __shared__ float t[32][33];
    int b = blockIdx.z, c0 = blockIdx.x*32, n0 = blockIdx.y*32;
    int tx = threadIdx.x, ty = threadIdx.y;
    #pragma unroll
    for (int i = 0; i < 32; i += 8)
        t[ty+i][tx] = g_outT[b*N_*C_ + (n0 + ty + i)*C_ + c0 + tx];
    __syncthreads();
    #pragma unroll
    for (int i = 0; i < 32; i += 8)
        out[b*C_*N_ + (c0 + ty + i)*N_ + n0 + tx] = t[tx][ty+i];
}

// ----------------------------- k_main -----------------------------
#define MCHUNKS 16
__global__ void __launch_bounds__(256) k_main(const float* __restrict__ alpha_p,
                                              const float* __restrict__ fuse_b,
                                              const float* __restrict__ ln_g,
                                              const float* __restrict__ ln_b) {
    extern __shared__ float sm[];
    float* s_pkT = sm;                         // 64*257
    float* s_rfv = s_pkT + 64*257;             // 32*256
    float* s_rk  = s_rfv + 32*256;             // 32*65
    int*   s_pool= (int*)(s_rk + 32*65);       // 256

    int reg = blockIdx.y, b = blockIdx.z;
    int cnt = g_cnt[b*K_ + reg];
    if ((int)blockIdx.x * 64 >= cnt) return;
    int tid = threadIdx.x, lane = tid & 31, w = tid >> 5;

    if (tid < M_) s_pool[tid] = g_ti[(b*K_+reg)*M_ + tid];
    __syncthreads();
    #pragma unroll 4
    for (int i = 0; i < 64; i++) {
        int e = tid + i*256;
        int m = e >> 6, d = e & 63;
        s_pkT[d*257 + m] = g_kT[(b*N_ + s_pool[m])*D_ + d];
    }
    #pragma unroll
    for (int i = 0; i < 32; i++) s_rfv[tid + i*256] = g_RFV[b*K_*C_ + tid + i*256];
    #pragma unroll
    for (int i = 0; i < 8; i++) {
        int e = tid + i*256; int kk = e >> 6, d = e & 63;
        s_rk[kk*65+d] = g_RK[(b*K_+kk)*D_ + d];
    }
    __syncthreads();

    float a = 1.f/(1.f + expf(-alpha_p[0]));

    for (int chunk = blockIdx.x; chunk*64 < cnt; chunk += MCHUNKS) {
        int base = chunk*64;
        int pend = min(base+64, cnt);
        for (int g = 0; g < 2; g++) {
            int p0 = base + w*8 + g*4;
            if (p0 >= pend) break;
            int nv = min(4, pend - p0);
            int n[4]; float q0[4], q1[4];
            #pragma unroll
            for (int i = 0; i < 4; i++) {
                if (i < nv) {
                    n[i] = g_plist[(b*K_+reg)*N_ + p0 + i];
                    q0[i] = g_qT[(b*N_+n[i])*D_ + lane];
                    q1[i] = g_qT[(b*N_+n[i])*D_ + 32 + lane];
                } else { n[i] = 0; q0[i] = 0.f; q1[i] = 0.f; }
            }

            float sims[4][8] = {};
            #pragma unroll
            for (int dh = 0; dh < 2; dh++) {
                #pragma unroll 2
                for (int dd = 0; dd < 32; dd++) {
                    const float* rowp = s_pkT + (dh*32+dd)*257;
                    float r8[8];
                    #pragma unroll
                    for (int mi = 0; mi < 8; mi++) r8[mi] = rowp[mi*32 + lane];
                    #pragma unroll
                    for (int i = 0; i < 4; i++) {
                        float qd = __shfl_sync(0xFFFFFFFFu, dh ? q1[i] : q0[i], dd);
                        #pragma unroll
                        for (int mi = 0; mi < 8; mi++) sims[i][mi] += qd * r8[mi];
                    }
                }
            }

            #pragma unroll 1
            for (int i = 0; i < 4; i++) {
                if (i >= nv) break;
                float sv[8];
                #pragma unroll
                for (int mi = 0; mi < 8; mi++) sv[mi] = sims[i][mi] * INVSCALE;

                float tv[8]; int tm[8];
                unsigned used = 0;
                #pragma unroll
                for (int t = 0; t < 8; t++) {
                    float bv = -INFINITY; int bm = 1 << 30;
                    #pragma unroll
                    for (int mi = 0; mi < 8; mi++) {
                        if (!(used & (1u << mi))) {
                            float v = sv[mi]; int m = mi*32 + lane;
                            if (v > bv || (v == bv && m < bm)) { bv = v; bm = m; }
                        }
                    }
                    #pragma unroll
                    for (int off = 16; off > 0; off >>= 1) {
                        float ov = __shfl_xor_sync(0xFFFFFFFFu, bv, off);
                        int   om = __shfl_xor_sync(0xFFFFFFFFu, bm, off);
                        if (ov > bv || (ov == bv && om < bm)) { bv = ov; bm = om; }
                    }
                    tv[t] = bv; tm[t] = bm;
                    if ((bm & 31) == lane) used |= 1u << (bm >> 5);
                }
                float ww[8], wsum = 0.f;
                #pragma unroll
                for (int t = 0; t < 8; t++) { ww[t] = expf(tv[t] - tv[0]); wsum += ww[t]; }
                float winv = 1.f/wsum;
                float fs[8] = {};
                #pragma unroll
                for (int t = 0; t < 8; t++) {
                    float att = ww[t]*winv;
                    int gidx = s_pool[tm[t]];
                    const float* fvrow = g_fvT + (b*N_ + gidx)*C_;
                    #pragma unroll
                    for (int j = 0; j < 8; j++) fs[j] += att * fvrow[j*32 + lane];
                }
                float lg = 0.f;
                #pragma unroll
                for (int dh = 0; dh < 2; dh++) {
                    #pragma unroll 4
                    for (int dd = 0; dd < 32; dd++) {
                        float qd = __shfl_sync(0xFFFFFFFFu, dh ? q1[i] : q0[i], dd);
                        lg += qd * s_rk[lane*65 + dh*32 + dd];
                    }
                }
                lg *= INVSCALE;
                float mx = lg;
                #pragma unroll
                for (int off = 16; off > 0; off >>= 1)
                    mx = fmaxf(mx, __shfl_xor_sync(0xFFFFFFFFu, mx, off));
                float ev = expf(lg - mx), es = ev;
                #pragma unroll
                for (int off = 16; off > 0; off >>= 1) es += __shfl_xor_sync(0xFFFFFFFFu, es, off);
                float attn = ev/es;
                float fc[8] = {};
                #pragma unroll 4
                for (int kk = 0; kk < K_; kk++) {
                    float ak = __shfl_sync(0xFFFFFFFFu, attn, kk);
                    const float* rrow = s_rfv + kk*256;
                    #pragma unroll
                    for (int j = 0; j < 8; j++) fc[j] += ak * rrow[j*32 + lane];
                }
                float pre[8], sum = 0.f, sq = 0.f;
                const float* xrow = g_xT + (b*N_+n[i])*C_;
                #pragma unroll
                for (int j = 0; j < 8; j++) {
                    int c = j*32 + lane;
                    float f = a*fc[j] + (1.f - a)*fs[j] + fuse_b[c];
                    float v = xrow[c] + f;
                    pre[j] = v; sum += v; sq += v*v;
                }
                #pragma unroll
                for (int off = 16; off > 0; off >>= 1) {
                    sum += __shfl_xor_sync(0xFFFFFFFFu, sum, off);
                    sq  += __shfl_xor_sync(0xFFFFFFFFu, sq,  off);
                }
                float mu = sum * (1.f/256.f);
                float var = sq * (1.f/256.f) - mu*mu;
                float rstd = rsqrtf(var + 1e-5f);
                float* orow = g_outT + (b*N_+n[i])*C_;
                #pragma unroll
                for (int j = 0; j < 8; j++) {
                    int c = j*32 + lane;
                    orow[c] = (pre[j]-mu)*rstd*ln_g[c] + ln_b[c];
                }
            }
        }
    }
}

// ----------------------------- launch -----------------------------
extern "C" void kernel_launch(void* const* d_in, const int* in_sizes, int n_in,
                              void* d_out, int out_size) {
    const float* x      = (const float*)d_in[0];
    const float* sem_w  = (const float*)d_in[1];
    const float* sem_b  = (const float*)d_in[2];
    const float* q_w    = (const float*)d_in[3];
    const float* k_w    = (const float*)d_in[4];
    const float* v_w    = (const float*)d_in[5];
    const float* fuse_w = (const float*)d_in[6];
    const float* fuse_b = (const float*)d_in[7];
    const float* alpha  = (const float*)d_in[8];
    const float* ln_g   = (const float*)d_in[9];
    const float* ln_b   = (const float*)d_in[10];
    float* out = (float*)d_out;

    const int SMEM_MAIN = (64*257 + 32*256 + 32*65)*4 + 256*4;
    cudaFuncSetAttribute((const void*)k_main,
                         cudaFuncAttributeMaxDynamicSharedMemorySize, SMEM_MAIN);
    cudaFuncSetAttribute((const void*)k_gemm,
                         cudaFuncAttributeMaxDynamicSharedMemorySize, GEMM_SMEM);

    k_pre<<<1114, 256>>>(x, sem_w, sem_b, q_w, k_w, v_w, fuse_w); // #1
    k_gemm<<<dim3(32, 4, B_), 256, GEMM_SMEM>>>();                // #2
    k_sem<<<128, 256>>>();                                        // #3
    k_region<<<dim3(5, 16, B_), 256>>>();                         // #4  <- ncu slot
    k_sel<<<B_*K_, 512>>>();                                      // #5
    k_main<<<dim3(MCHUNKS, K_, B_), 256, SMEM_MAIN>>>(alpha, fuse_b, ln_g, ln_b); // #6
    k_transpO<<<dim3(8, 128, B_), dim3(32, 8)>>>(out);            // #7
}

// round 13
// speedup vs baseline: 1.2168x; 1.1897x over previous
#include <cuda_runtime.h>
#include <cuda_bf16.h>
#include <math.h>

#define B_ 2
#define C_ 256
#define N_ 4096
#define D_ 64
#define K_ 32
#define M_ 256
#define R_ 416
#define RP2 512
#define INVSCALE (1.0f/8.000001f)
typedef unsigned long long ull;
typedef unsigned int uint;

// ----------------------------- scratch -----------------------------
__device__ __align__(16) __nv_bfloat16 g_Wh[RP2*C_];
__device__ __align__(16) __nv_bfloat16 g_Wl[RP2*C_];
__device__ __align__(16) __nv_bfloat16 g_xh[B_*C_*N_];
__device__ __align__(16) __nv_bfloat16 g_xl[B_*C_*N_];
__device__ float g_bias[R_];
__device__ float g_P[B_*R_*N_];        // [sem(32); q(64); k(64); fv(256)] x N
__device__ float g_sem[B_*K_*N_];
__device__ int   g_ti[B_*K_*M_];
__device__ int   g_cnt[B_*K_];
__device__ int   g_plist[B_*K_*N_];
__device__ float g_qT[B_*N_*D_];
__device__ float g_kT[B_*N_*D_];
__device__ float g_fvT[B_*N_*C_];
__device__ float g_xT[B_*N_*C_];
__device__ float g_RK[B_*K_*D_];
__device__ float g_RFV[B_*K_*C_];
__device__ float g_outT[B_*N_*C_];

__device__ __forceinline__ void split_bf16(float v, __nv_bfloat16& h, __nv_bfloat16& l) {
    h = __float2bfloat16_rn(v);
    l = __float2bfloat16_rn(v - __bfloat162float(h));
}
__device__ __forceinline__ uint cvta_smem(const void* p) {
    return (uint)__cvta_generic_to_shared(p);
}

// ----------------------------- k_pre (fused zero + cvtx + prep) -----------------------------
__global__ void __launch_bounds__(256) k_pre(
    const float* __restrict__ x,
    const float* __restrict__ sem_w, const float* __restrict__ sem_b,
    const float* __restrict__ q_w,  const float* __restrict__ k_w,
    const float* __restrict__ v_w,  const float* __restrict__ fuse_w) {
    int bx = blockIdx.x, tid = threadIdx.x;
    if (bx < 1024) {
        __shared__ float t[64][33];
        int n0 = (bx & 63)*64, c0 = ((bx >> 6) & 7)*32, b = bx >> 9;
        int tx = tid & 31, ty = tid >> 5;
        #pragma unroll
        for (int i = 0; i < 4; i++) {
            int c = c0 + ty + i*8;
            int n = n0 + tx*2;
            float2 v = *(const float2*)&x[(b*C_ + c)*N_ + n];
            __nv_bfloat16 h0, l0, h1, l1;
            split_bf16(v.x, h0, l0); split_bf16(v.y, h1, l1);
            uint hw = (uint)__bfloat16_as_ushort(h0) | ((uint)__bfloat16_as_ushort(h1) << 16);
            uint lw = (uint)__bfloat16_as_ushort(l0) | ((uint)__bfloat16_as_ushort(l1) << 16);
            *(uint*)&g_xh[(b*C_ + c)*N_ + n] = hw;
            *(uint*)&g_xl[(b*C_ + c)*N_ + n] = lw;
            t[tx*2][ty + i*8]     = v.x;
            t[tx*2 + 1][ty + i*8] = v.y;
        }
        __syncthreads();
        #pragma unroll
        for (int i = 0; i < 8; i++) {
            int nn = ty + i*8;
            g_xT[(b*N_ + n0 + nn)*C_ + c0 + tx] = t[nn][tx];
        }
    } else if (bx < 1066) {
        int blk = bx - 1024;
        if (blk < 10) {
            #pragma unroll
            for (int it = 0; it < 16; it++) {
                int e = tid + it*256;
                int r = blk*16 + (e >> 8), c = e & 255;
                float val = (r < 32) ? sem_w[r*C_ + c]
                          : (r < 96) ? q_w[(r-32)*C_ + c]
                                     : k_w[(r-96)*C_ + c];
                __nv_bfloat16 h, l; split_bf16(val, h, l);
                g_Wh[r*C_ + c] = h; g_Wl[r*C_ + c] = l;
                if (c == 0) g_bias[r] = (r < 32) ? sem_b[r] : 0.f;
            }
        } else {
            int r0 = 160 + (blk-10)*8;
            __shared__ float fw[8*256];
            #pragma unroll
            for (int it = 0; it < 8; it++) {
                int e = tid + it*256;
                fw[e] = fuse_w[(r0-160)*C_ + e];
            }
            __syncthreads();
            float acc[8] = {};
            for (int m = 0; m < C_; m++) {
                float v = v_w[m*C_ + tid];
                #pragma unroll
                for (int rr = 0; rr < 8; rr++) acc[rr] += fw[rr*256 + m] * v;
            }
            #pragma unroll
            for (int rr = 0; rr < 8; rr++) {
                int r = r0 + rr;
                __nv_bfloat16 h, l; split_bf16(acc[rr], h, l);
                g_Wh[r*C_ + tid] = h; g_Wl[r*C_ + tid] = l;
                if (tid == 0) g_bias[r] = 0.f;
            }
        }
    } else {
        int w = (bx - 1066)*256 + tid;          // 48*256 = 12288
        ((uint*)g_Wh)[53248 + w] = 0;
        ((uint*)g_Wl)[53248 + w] = 0;
        if (w < 4096) ((float*)g_RK)[w] = 0.f;
        if (w < 8192) { g_RFV[w] = 0.f; g_RFV[w + 8192] = 0.f; }
        if (w < B_*K_) g_cnt[w] = 0;
    }
}

// ----------------------------- k_gemm (3-stage cp.async + ldmatrix, fused transpose epilogue) ---
__device__ __forceinline__ void mma16816(float* d, const uint* a, uint b0, uint b1) {
    asm volatile(
        "mma.sync.aligned.m16n8k16.row.col.f32.bf16.bf16.f32 "
        "{%0,%1,%2,%3}, {%4,%5,%6,%7}, {%8,%9}, {%0,%1,%2,%3};"
        : "+f"(d[0]), "+f"(d[1]), "+f"(d[2]), "+f"(d[3])
        : "r"(a[0]), "r"(a[1]), "r"(a[2]), "r"(a[3]), "r"(b0), "r"(b1));
}
__device__ __forceinline__ void ldsm4(uint* r, uint addr) {
    asm volatile("ldmatrix.sync.aligned.m8n8.x4.shared.b16 {%0,%1,%2,%3}, [%4];"
        : "=r"(r[0]), "=r"(r[1]), "=r"(r[2]), "=r"(r[3]) : "r"(addr));
}
__device__ __forceinline__ void ldsm4t(uint* r, uint addr) {
    asm volatile("ldmatrix.sync.aligned.m8n8.x4.trans.shared.b16 {%0,%1,%2,%3}, [%4];"
        : "=r"(r[0]), "=r"(r[1]), "=r"(r[2]), "=r"(r[3]) : "r"(addr));
}
__device__ __forceinline__ void cpa16(uint dst, const void* src) {
    asm volatile("cp.async.cg.shared.global [%0], [%1], 16;" :: "r"(dst), "l"(src));
}

#define A_ST_BYTES (128*40*2)
#define B_ST_BYTES (32*136*2)
#define SB_BASE_OFF (6*A_ST_BYTES)
#define GEMM_SMEM (6*A_ST_BYTES + 6*B_ST_BYTES)

__device__ __forceinline__ void gemm_load(int st, int kc, int r0, int n0,
                                          const __nv_bfloat16* xh, const __nv_bfloat16* xl,
                                          uint sa_base, uint sb_base, int tid) {
    #pragma unroll
    for (int i = 0; i < 4; i++) {
        int ch = tid + i*256;
        int hl = ch >> 9, rem = ch & 511;
        int r = rem >> 2, c = (rem & 3)*8;
        const __nv_bfloat16* src = (hl ? g_Wl : g_Wh) + (r0 + r)*C_ + kc + c;
        cpa16(sa_base + (st*2 + hl)*A_ST_BYTES + (r*40 + c)*2, src);
    }
    #pragma unroll
    for (int i = 0; i < 4; i++) {
        int ch = tid + i*256;
        int hl = ch >> 9, rem = ch & 511;
        int k = rem >> 4, c = (rem & 15)*8;
        const __nv_bfloat16* src = (hl ? xl : xh) + (kc + k)*N_ + n0 + c;
        cpa16(sb_base + (st*2 + hl)*B_ST_BYTES + (k*136 + c)*2, src);
    }
    asm volatile("cp.async.commit_group;" ::: "memory");
}

__global__ void __launch_bounds__(256) k_gemm() {
    extern __shared__ __align__(16) char dsm[];
    uint sa_base = cvta_smem(dsm);
    uint sb_base = sa_base + SB_BASE_OFF;

    int n0 = blockIdx.x*128, r0 = blockIdx.y*128, b = blockIdx.z;
    int tid = threadIdx.x, lane = tid & 31, wid = tid >> 5;
    int wm = wid & 3, wn = wid >> 2;
    const __nv_bfloat16* xh = g_xh + b*C_*N_;
    const __nv_bfloat16* xl = g_xl + b*C_*N_;

    float acc[2][8][4];
    #pragma unroll
    for (int mt = 0; mt < 2; mt++)
        #pragma unroll
        for (int nt = 0; nt < 8; nt++)
            #pragma unroll
            for (int i = 0; i < 4; i++) acc[mt][nt][i] = 0.f;

    gemm_load(0, 0,  r0, n0, xh, xl, sa_base, sb_base, tid);
    gemm_load(1, 32, r0, n0, xh, xl, sa_base, sb_base, tid);

    for (int kt = 0; kt < 8; kt++) {
        if (kt < 7) asm volatile("cp.async.wait_group 1;" ::: "memory");
        else        asm volatile("cp.async.wait_group 0;" ::: "memory");
        __syncthreads();
        int st = kt % 3;
        uint sa0 = sa_base + (st*2+0)*A_ST_BYTES;
        uint sa1 = sa_base + (st*2+1)*A_ST_BYTES;
        uint sb0 = sb_base + (st*2+0)*B_ST_BYTES;
        uint sb1 = sb_base + (st*2+1)*B_ST_BYTES;
        #pragma unroll
        for (int k16 = 0; k16 < 2; k16++) {
            uint ah0[4], ah1[4], al0[4], al1[4];
            int ra = wm*32 + (lane & 15);
            int kcol = k16*16 + (lane >> 4)*8;
            ldsm4(ah0, sa0 + (ra*40 + kcol)*2);
            ldsm4(ah1, sa0 + ((ra+16)*40 + kcol)*2);
            ldsm4(al0, sa1 + (ra*40 + kcol)*2);
            ldsm4(al1, sa1 + ((ra+16)*40 + kcol)*2);
            int krow = k16*16 + (lane & 15);
            #pragma unroll
            for (int np = 0; np < 4; np++) {
                int nc = wn*64 + np*16 + (lane >> 4)*8;
                uint bh[4], bl[4];
                ldsm4t(bh, sb0 + (krow*136 + nc)*2);
                ldsm4t(bl, sb1 + (krow*136 + nc)*2);
                mma16816(acc[0][np*2],   ah0, bh[0], bh[1]);
                mma16816(acc[1][np*2],   ah1, bh[0], bh[1]);
                mma16816(acc[0][np*2+1], ah0, bh[2], bh[3]);
                mma16816(acc[1][np*2+1], ah1, bh[2], bh[3]);
                mma16816(acc[0][np*2],   ah0, bl[0], bl[1]);
                mma16816(acc[1][np*2],   ah1, bl[0], bl[1]);
                mma16816(acc[0][np*2+1], ah0, bl[2], bl[3]);
                mma16816(acc[1][np*2+1], ah1, bl[2], bl[3]);
                mma16816(acc[0][np*2],   al0, bh[0], bh[1]);
                mma16816(acc[1][np*2],   al1, bh[0], bh[1]);
                mma16816(acc[0][np*2+1], al0, bh[2], bh[3]);
                mma16816(acc[1][np*2+1], al1, bh[2], bh[3]);
            }
        }
        __syncthreads();
        if (kt + 2 < 8)
            gemm_load((kt+2) % 3, (kt+2)*32, r0, n0, xh, xl, sa_base, sb_base, tid);
    }

    float* T = (float*)dsm;                 // 128 x 133 floats
    #pragma unroll
    for (int mt = 0; mt < 2; mt++) {
        int rl = wm*32 + mt*16 + (lane >> 2);
        int r = r0 + rl;
        float bi0 = (r < R_) ? g_bias[r] : 0.f;
        float bi1 = (r + 8 < R_) ? g_bias[r + 8] : 0.f;
        #pragma unroll
        for (int nt = 0; nt < 8; nt++) {
            int nl = wn*64 + nt*8 + (lane & 3)*2;
            float v0 = acc[mt][nt][0] + bi0, v1 = acc[mt][nt][1] + bi0;
            float v2 = acc[mt][nt][2] + bi1, v3 = acc[mt][nt][3] + bi1;
            T[rl*133 + nl] = v0; T[rl*133 + nl + 1] = v1;
            T[(rl+8)*133 + nl] = v2; T[(rl+8)*133 + nl + 1] = v3;
            if (r < R_ && !(r >= 32 && r < 96))
                *(float2*)&g_P[(b*R_ + r)*N_ + n0 + nl] = make_float2(v0, v1);
            if (r + 8 < R_ && !(r + 8 >= 32 && r + 8 < 96))
                *(float2*)&g_P[(b*R_ + r + 8)*N_ + n0 + nl] = make_float2(v2, v3);
        }
    }
    __syncthreads();
    for (int i = 0; i < 64; i++) {
        int e = tid + i*256;
        int rl = e & 127, nl = e >> 7;
        int r = r0 + rl;
        if (r >= 32 && r < R_) {
            float v = T[rl*133 + nl];
            int n = n0 + nl;
            if (r < 96)       g_qT[(b*N_ + n)*D_ + (r - 32)]  = v;
            else if (r < 160) g_kT[(b*N_ + n)*D_ + (r - 96)]  = v;
            else              g_fvT[(b*N_ + n)*C_ + (r - 160)] = v;
        }
    }
}

// ----------------------------- k_sem -----------------------------
__global__ void __launch_bounds__(256) k_sem() {
    int g = blockIdx.x*256 + threadIdx.x;
    int pos = g >> 2, s = g & 3;
    int b = pos >> 12, n = pos & (N_-1);
    float l[8];
    float mx = -INFINITY; int am = K_;
    #pragma unroll
    for (int j = 0; j < 8; j++) {
        l[j] = g_P[(b*R_ + s*8 + j)*N_ + n];
        if (l[j] > mx) { mx = l[j]; am = s*8 + j; }
    }
    #pragma unroll
    for (int off = 1; off <= 2; off <<= 1) {
        float ov = __shfl_xor_sync(0xFFFFFFFFu, mx, off);
        int   oa = __shfl_xor_sync(0xFFFFFFFFu, am, off);
        if (ov > mx || (ov == mx && oa < am)) { mx = ov; am = oa; }
    }
    float sum = 0.f;
    #pragma unroll
    for (int j = 0; j < 8; j++) { l[j] = expf(l[j] - mx); sum += l[j]; }
    #pragma unroll
    for (int off = 1; off <= 2; off <<= 1)
        sum += __shfl_xor_sync(0xFFFFFFFFu, sum, off);
    float inv = 1.f/sum;
    #pragma unroll
    for (int j = 0; j < 8; j++) g_sem[(b*K_ + s*8 + j)*N_ + n] = l[j]*inv;
    if (s == 0) {
        int slot = atomicAdd(&g_cnt[b*K_ + am], 1);
        g_plist[(b*K_+am)*N_ + slot] = n;
    }
}

// ----------------------------- k_region (sp=32 for occupancy) -----------------------------
__global__ void __launch_bounds__(256) k_region() {
    __shared__ float ss[32*68];
    __shared__ float ps[64*68];
    int ct = blockIdx.x, sp = blockIdx.y, b = blockIdx.z;
    int tid = threadIdx.x;
    int kk = tid & 31, cg = tid >> 5;
    float acc[8] = {};
    for (int nch = 0; nch < 2; nch++) {
        int nn0 = sp*128 + nch*64;
        #pragma unroll
        for (int i = 0; i < 8; i++) {
            int e = tid + i*256; int kr = e >> 6, nn = e & 63;
            ss[kr*68+nn] = g_sem[(b*K_+kr)*N_ + nn0 + nn];
        }
        #pragma unroll
        for (int i = 0; i < 16; i++) {
            int e = tid + i*256; int c = e >> 6, nn = e & 63;
            ps[c*68+nn] = g_P[(b*R_ + 96 + ct*64 + c)*N_ + nn0 + nn];
        }
        __syncthreads();
        #pragma unroll 4
        for (int nn = 0; nn < 64; nn += 4) {
            float4 sv = *(const float4*)&ss[kk*68 + nn];
            #pragma unroll
            for (int j = 0; j < 8; j++) {
                float4 pv = *(const float4*)&ps[(cg*8+j)*68 + nn];
                acc[j] += sv.x*pv.x;
                acc[j] += sv.y*pv.y;
                acc[j] += sv.z*pv.z;
                acc[j] += sv.w*pv.w;
            }
        }
        __syncthreads();
    }
    #pragma unroll
    for (int j = 0; j < 8; j++) {
        int o = ct*64 + cg*8 + j;
        if (o < 64) atomicAdd(&g_RK[(b*K_+kk)*D_ + o], acc[j]);
        else        atomicAdd(&g_RFV[(b*K_+kk)*C_ + (o-64)], acc[j]);
    }
}

// ----------------------------- k_sel -----------------------------
__global__ void __launch_bounds__(512) k_sel() {
    __shared__ ull cand[4096];
    __shared__ ull win[256];
    __shared__ int sufc[256];
    __shared__ int s_tc, s_cA, s_t, s_A, s_nw, s_nc;
    unsigned* hist = (unsigned*)cand;

    int bk = blockIdx.x; int b = bk >> 5, k = bk & 31;
    int tid = threadIdx.x;
    const float* row = g_sem + (b*K_ + k)*N_;

    for (int i = tid; i < 4096; i += 512) hist[i] = 0;
    __syncthreads();

    unsigned vb[8];
    #pragma unroll
    for (int j = 0; j < 8; j++) {
        vb[j] = __float_as_uint(row[tid + j*512]);
        atomicAdd(&hist[vb[j] >> 20], 1);
    }
    __syncthreads();

    if (tid < 256) {
        int cs = 0;
        #pragma unroll
        for (int h = 0; h < 16; h++) cs += hist[tid*16 + h];
        sufc[tid] = cs;
    }
    __syncthreads();
    #pragma unroll
    for (int st = 1; st < 256; st <<= 1) {
        int add = (tid < 256 && tid + st < 256) ? sufc[tid + st] : 0;
        __syncthreads();
        if (tid < 256) sufc[tid] += add;
        __syncthreads();
    }
    if (tid < 256) {
        int nxt = (tid < 255) ? sufc[tid + 1] : 0;
        if (sufc[tid] >= M_ && nxt < M_) { s_tc = tid; s_cA = nxt; }
    }
    if (tid == 0) { s_nw = 0; s_nc = 0; }
    __syncthreads();
    int tc = s_tc, cA = s_cA;
    if (tid < 16) {
        int sg = 0;
        for (int j = tid; j < 16; j++) sg += hist[tc*16 + j];
        int hi = hist[tc*16 + tid];
        if (cA + sg >= M_ && cA + sg - hi < M_) { s_t = tc*16 + tid; s_A = cA + sg - hi; }
    }
    __syncthreads();
    int t = s_t, A = s_A, s = M_ - A;
    __syncthreads();

    #pragma unroll
    for (int j = 0; j < 8; j++) {
        unsigned v = vb[j];
        int idx = tid + j*512;
        unsigned bkt = v >> 20;
        ull key = ((ull)v << 32) | (unsigned)(0xFFFFFFFFu - (unsigned)idx);
        if ((int)bkt > t) { int p = atomicAdd(&s_nw, 1); win[p] = ~key; }
        else if ((int)bkt == t) { int p = atomicAdd(&s_nc, 1); cand[p] = ~key; }
    }
    __syncthreads();

    int nc = s_nc;
    int P = 1; while (P < nc) P <<= 1;
    for (int i = tid; i < P; i += 512) if (i >= nc) cand[i] = 0xFFFFFFFFFFFFFFFFULL;
    __syncthreads();
    for (int sz = 2; sz <= P; sz <<= 1) {
        for (int str = sz >> 1; str > 0; str >>= 1) {
            for (int i = tid; i < P; i += 512) {
                int l = i ^ str;
                if (l > i) {
                    ull a = cand[i], c2 = cand[l];
                    bool up = ((i & sz) == 0);
                    if ((a > c2) == up) { cand[i] = c2; cand[l] = a; }
                }
            }
            __syncthreads();
        }
    }
    for (int i = tid; i < s; i += 512) win[A + i] = cand[i];
    __syncthreads();
    for (int sz = 2; sz <= 256; sz <<= 1) {
        for (int str = sz >> 1; str > 0; str >>= 1) {
            if (tid < 256) {
                int i = tid, l = i ^ str;
                if (l > i) {
                    ull a = win[i], c2 = win[l];
                    bool up = ((i & sz) == 0);
                    if ((a > c2) == up) { win[i] = c2; win[l] = a; }
                }
            }
            __syncthreads();
        }
    }
    if (tid < 256) g_ti[(b*K_ + k)*M_ + tid] = (int)(unsigned)(win[tid] & 0xFFFFFFFFu);
}

// ----------------------------- k_transpO -----------------------------
__global__ void k_transpO(float* __restrict__ out) {
    __shared__ float t[32][33];
    int b = blockIdx.z, c0 = blockIdx.x*32, n0 = blockIdx.y*32;
    int tx = threadIdx.x, ty = threadIdx.y;
    #pragma unroll
    for (int i = 0; i < 32; i += 8)
        t[ty+i][tx] = g_outT[b*N_*C_ + (n0 + ty + i)*C_ + c0 + tx];
    __syncthreads();
    #pragma unroll
    for (int i = 0; i < 32; i += 8)
        out[b*C_*N_ + (c0 + ty + i)*N_ + n0 + tx] = t[tx][ty+i];
}

// ----------------------------- k_main (chunk=32, 4 pos/warp, batched dense) -----------------------------
#define MCH 32
__global__ void __launch_bounds__(256) k_main(const float* __restrict__ alpha_p,
                                              const float* __restrict__ fuse_b,
                                              const float* __restrict__ ln_g,
                                              const float* __restrict__ ln_b) {
    extern __shared__ float sm[];
    float* s_pkT = sm;                         // 64*257
    float* s_rfv = s_pkT + 64*257;             // 32*256
    float* s_rk  = s_rfv + 32*256;             // 32*65
    int*   s_pool= (int*)(s_rk + 32*65);       // 256

    int reg = blockIdx.y, b = blockIdx.z;
    int cnt = g_cnt[b*K_ + reg];
    if ((int)blockIdx.x * 32 >= cnt) return;
    int tid = threadIdx.x, lane = tid & 31, w = tid >> 5;

    if (tid < M_) s_pool[tid] = g_ti[(b*K_+reg)*M_ + tid];
    __syncthreads();
    #pragma unroll 4
    for (int i = 0; i < 64; i++) {
        int e = tid + i*256;
        int m = e >> 6, d = e & 63;
        s_pkT[d*257 + m] = g_kT[(b*N_ + s_pool[m])*D_ + d];
    }
    #pragma unroll
    for (int i = 0; i < 32; i++) s_rfv[tid + i*256] = g_RFV[b*K_*C_ + tid + i*256];
    #pragma unroll
    for (int i = 0; i < 8; i++) {
        int e = tid + i*256; int kk = e >> 6, d = e & 63;
        s_rk[kk*65+d] = g_RK[(b*K_+kk)*D_ + d];
    }
    __syncthreads();

    float a = 1.f/(1.f + expf(-alpha_p[0]));
    float one_a = 1.f - a;

    for (int chunk = blockIdx.x; chunk*32 < cnt; chunk += MCH) {
        int base = chunk*32;
        int pend = min(base+32, cnt);
        int p0 = base + w*4;
        if (p0 >= pend) continue;
        int nv = min(4, pend - p0);
        int n[4]; float q0[4], q1[4];
        #pragma unroll
        for (int i = 0; i < 4; i++) {
            if (i < nv) {
                n[i] = g_plist[(b*K_+reg)*N_ + p0 + i];
                q0[i] = g_qT[(b*N_+n[i])*D_ + lane];
                q1[i] = g_qT[(b*N_+n[i])*D_ + 32 + lane];
            } else { n[i] = 0; q0[i] = 0.f; q1[i] = 0.f; }
        }

        // sims[i][mi] over the 256-entry pool; lane owns m = mi*32+lane
        float sims[4][8] = {};
        #pragma unroll
        for (int dh = 0; dh < 2; dh++) {
            #pragma unroll 2
            for (int dd = 0; dd < 32; dd++) {
                const float* rowp = s_pkT + (dh*32+dd)*257;
                float r8[8];
                #pragma unroll
                for (int mi = 0; mi < 8; mi++) r8[mi] = rowp[mi*32 + lane];
                #pragma unroll
                for (int i = 0; i < 4; i++) {
                    float qd = __shfl_sync(0xFFFFFFFFu, dh ? q1[i] : q0[i], dd);
                    #pragma unroll
                    for (int mi = 0; mi < 8; mi++) sims[i][mi] += qd * r8[mi];
                }
            }
        }

        // per-position: top-8 + softmax + sparse gather into cb[i] (scaled by 1-a)
        float cb[4][8];
        #pragma unroll 1
        for (int i = 0; i < 4; i++) {
            float sv[8];
            #pragma unroll
            for (int mi = 0; mi < 8; mi++) sv[mi] = sims[i][mi] * INVSCALE;

            float tv[8]; int tm[8];
            unsigned used = 0;
            #pragma unroll
            for (int t = 0; t < 8; t++) {
                float bv = -INFINITY; int bm = 1 << 30;
                #pragma unroll
                for (int mi = 0; mi < 8; mi++) {
                    if (!(used & (1u << mi))) {
                        float v = sv[mi]; int m = mi*32 + lane;
                        if (v > bv || (v == bv && m < bm)) { bv = v; bm = m; }
                    }
                }
                #pragma unroll
                for (int off = 16; off > 0; off >>= 1) {
                    float ov = __shfl_xor_sync(0xFFFFFFFFu, bv, off);
                    int   om = __shfl_xor_sync(0xFFFFFFFFu, bm, off);
                    if (ov > bv || (ov == bv && om < bm)) { bv = ov; bm = om; }
                }
                tv[t] = bv; tm[t] = bm;
                if ((bm & 31) == lane) used |= 1u << (bm >> 5);
            }
            float ww[8], wsum = 0.f;
            #pragma unroll
            for (int t = 0; t < 8; t++) { ww[t] = expf(tv[t] - tv[0]); wsum += ww[t]; }
            float winv = one_a/wsum;
            float fs[8] = {};
            #pragma unroll
            for (int t = 0; t < 8; t++) {
                float att = ww[t]*winv;
                int gidx = s_pool[tm[t]];
                const float* fvrow = g_fvT + (b*N_ + gidx)*C_;
                #pragma unroll
                for (int j = 0; j < 8; j++) fs[j] += att * fvrow[j*32 + lane];
            }
            #pragma unroll
            for (int j = 0; j < 8; j++) cb[i][j] = fs[j];
        }

        // batched dense logits: lg[i][k=lane] = q_i . rk[lane]
        float lg[4] = {0.f, 0.f, 0.f, 0.f};
        #pragma unroll
        for (int dh = 0; dh < 2; dh++) {
            #pragma unroll 4
            for (int dd = 0; dd < 32; dd++) {
                float rkv = s_rk[lane*65 + dh*32 + dd];
                #pragma unroll
                for (int i = 0; i < 4; i++) {
                    float qd = __shfl_sync(0xFFFFFFFFu, dh ? q1[i] : q0[i], dd);
                    lg[i] += qd * rkv;
                }
            }
        }
        // batched dense softmax over k (32 lanes), 4 interleaved chains
        float mx[4], es[4], aat[4];
        #pragma unroll
        for (int i = 0; i < 4; i++) { lg[i] *= INVSCALE; mx[i] = lg[i]; }
        #pragma unroll
        for (int off = 16; off > 0; off >>= 1) {
            #pragma unroll
            for (int i = 0; i < 4; i++)
                mx[i] = fmaxf(mx[i], __shfl_xor_sync(0xFFFFFFFFu, mx[i], off));
        }
        #pragma unroll
        for (int i = 0; i < 4; i++) { aat[i] = expf(lg[i] - mx[i]); es[i] = aat[i]; }
        #pragma unroll
        for (int off = 16; off > 0; off >>= 1) {
            #pragma unroll
            for (int i = 0; i < 4; i++)
                es[i] += __shfl_xor_sync(0xFFFFFFFFu, es[i], off);
        }
        #pragma unroll
        for (int i = 0; i < 4; i++) aat[i] = a*aat[i]/es[i];   // a * attn[k=lane]

        // batched fc accumulate into cb (4x SMEM reuse)
        #pragma unroll 4
        for (int kk = 0; kk < K_; kk++) {
            const float* rrow = s_rfv + kk*256;
            float r8[8];
            #pragma unroll
            for (int j = 0; j < 8; j++) r8[j] = rrow[j*32 + lane];
            #pragma unroll
            for (int i = 0; i < 4; i++) {
                float ak = __shfl_sync(0xFFFFFFFFu, aat[i], kk);
                #pragma unroll
                for (int j = 0; j < 8; j++) cb[i][j] += ak * r8[j];
            }
        }

        // per-position epilogue: bias + residual + channel LN
        #pragma unroll 1
        for (int i = 0; i < 4; i++) {
            if (i >= nv) break;
            float pre[8], sum = 0.f, sq = 0.f;
            const float* xrow = g_xT + (b*N_+n[i])*C_;
            #pragma unroll
            for (int j = 0; j < 8; j++) {
                int c = j*32 + lane;
                float v = xrow[c] + cb[i][j] + fuse_b[c];
                pre[j] = v; sum += v; sq += v*v;
            }
            #pragma unroll
            for (int off = 16; off > 0; off >>= 1) {
                sum += __shfl_xor_sync(0xFFFFFFFFu, sum, off);
                sq  += __shfl_xor_sync(0xFFFFFFFFu, sq,  off);
            }
            float mu = sum * (1.f/256.f);
            float var = sq * (1.f/256.f) - mu*mu;
            float rstd = rsqrtf(var + 1e-5f);
            float* orow = g_outT + (b*N_+n[i])*C_;
            #pragma unroll
            for (int j = 0; j < 8; j++) {
                int c = j*32 + lane;
                orow[c] = (pre[j]-mu)*rstd*ln_g[c] + ln_b[c];
            }
        }
    }
}

// ----------------------------- launch -----------------------------
extern "C" void kernel_launch(void* const* d_in, const int* in_sizes, int n_in,
                              void* d_out, int out_size) {
    const float* x      = (const float*)d_in[0];
    const float* sem_w  = (const float*)d_in[1];
    const float* sem_b  = (const float*)d_in[2];
    const float* q_w    = (const float*)d_in[3];
    const float* k_w    = (const float*)d_in[4];
    const float* v_w    = (const float*)d_in[5];
    const float* fuse_w = (const float*)d_in[6];
    const float* fuse_b = (const float*)d_in[7];
    const float* alpha  = (const float*)d_in[8];
    const float* ln_g   = (const float*)d_in[9];
    const float* ln_b   = (const float*)d_in[10];
    float* out = (float*)d_out;

    const int SMEM_MAIN = (64*257 + 32*256 + 32*65)*4 + 256*4;
    cudaFuncSetAttribute((const void*)k_main,
                         cudaFuncAttributeMaxDynamicSharedMemorySize, SMEM_MAIN);
    cudaFuncSetAttribute((const void*)k_gemm,
                         cudaFuncAttributeMaxDynamicSharedMemorySize, GEMM_SMEM);

    k_pre<<<1114, 256>>>(x, sem_w, sem_b, q_w, k_w, v_w, fuse_w); // #1
    k_gemm<<<dim3(32, 4, B_), 256, GEMM_SMEM>>>();                // #2
    k_sem<<<128, 256>>>();                                        // #3
    k_region<<<dim3(5, 32, B_), 256>>>();                         // #4  <- ncu slot
    k_sel<<<B_*K_, 512>>>();                                      // #5
    k_main<<<dim3(MCH, K_, B_), 256, SMEM_MAIN>>>(alpha, fuse_b, ln_g, ln_b); // #6
    k_transpO<<<dim3(8, 128, B_), dim3(32, 8)>>>(out);            // #7
}

// round 14
// speedup vs baseline: 1.3452x; 1.1055x over previous
#include <cuda_runtime.h>
#include <cuda_bf16.h>
#include <math.h>

#define B_ 2
#define C_ 256
#define N_ 4096
#define D_ 64
#define K_ 32
#define M_ 256
#define R_ 416
#define RP2 512
#define INVSCALE (1.0f/8.000001f)
typedef unsigned long long ull;
typedef unsigned int uint;

// ----------------------------- scratch -----------------------------
__device__ __align__(16) __nv_bfloat16 g_Wh[RP2*C_];
__device__ __align__(16) __nv_bfloat16 g_Wl[RP2*C_];
__device__ __align__(16) __nv_bfloat16 g_xh[B_*C_*N_];
__device__ __align__(16) __nv_bfloat16 g_xl[B_*C_*N_];
__device__ float g_bias[R_];
__device__ float g_P[B_*R_*N_];        // rows 96..415 used: [k(64); fv(256)]
__device__ float g_sem[B_*K_*N_];
__device__ int   g_ti[B_*K_*M_];
__device__ int   g_cnt[B_*K_];
__device__ int   g_plist[B_*K_*N_];
__device__ float g_qT[B_*N_*D_];
__device__ float g_kT[B_*N_*D_];
__device__ float g_fvT[B_*N_*C_];
__device__ float g_xT[B_*N_*C_];
__device__ float g_RK[B_*K_*D_];
__device__ float g_RFV[B_*K_*C_];
__device__ float g_outT[B_*N_*C_];

__device__ __forceinline__ void split_bf16(float v, __nv_bfloat16& h, __nv_bfloat16& l) {
    h = __float2bfloat16_rn(v);
    l = __float2bfloat16_rn(v - __bfloat162float(h));
}
__device__ __forceinline__ uint cvta_smem(const void* p) {
    return (uint)__cvta_generic_to_shared(p);
}

// ----------------------------- k_pre (fused zero + cvtx + prep) -----------------------------
__global__ void __launch_bounds__(256) k_pre(
    const float* __restrict__ x,
    const float* __restrict__ sem_w, const float* __restrict__ sem_b,
    const float* __restrict__ q_w,  const float* __restrict__ k_w,
    const float* __restrict__ v_w,  const float* __restrict__ fuse_w) {
    int bx = blockIdx.x, tid = threadIdx.x;
    if (bx < 1024) {
        __shared__ float t[64][33];
        int n0 = (bx & 63)*64, c0 = ((bx >> 6) & 7)*32, b = bx >> 9;
        int tx = tid & 31, ty = tid >> 5;
        #pragma unroll
        for (int i = 0; i < 4; i++) {
            int c = c0 + ty + i*8;
            int n = n0 + tx*2;
            float2 v = *(const float2*)&x[(b*C_ + c)*N_ + n];
            __nv_bfloat16 h0, l0, h1, l1;
            split_bf16(v.x, h0, l0); split_bf16(v.y, h1, l1);
            uint hw = (uint)__bfloat16_as_ushort(h0) | ((uint)__bfloat16_as_ushort(h1) << 16);
            uint lw = (uint)__bfloat16_as_ushort(l0) | ((uint)__bfloat16_as_ushort(l1) << 16);
            *(uint*)&g_xh[(b*C_ + c)*N_ + n] = hw;
            *(uint*)&g_xl[(b*C_ + c)*N_ + n] = lw;
            t[tx*2][ty + i*8]     = v.x;
            t[tx*2 + 1][ty + i*8] = v.y;
        }
        __syncthreads();
        #pragma unroll
        for (int i = 0; i < 8; i++) {
            int nn = ty + i*8;
            g_xT[(b*N_ + n0 + nn)*C_ + c0 + tx] = t[nn][tx];
        }
    } else if (bx < 1066) {
        int blk = bx - 1024;
        if (blk < 10) {
            #pragma unroll
            for (int it = 0; it < 16; it++) {
                int e = tid + it*256;
                int r = blk*16 + (e >> 8), c = e & 255;
                float val = (r < 32) ? sem_w[r*C_ + c]
                          : (r < 96) ? q_w[(r-32)*C_ + c]
                                     : k_w[(r-96)*C_ + c];
                __nv_bfloat16 h, l; split_bf16(val, h, l);
                g_Wh[r*C_ + c] = h; g_Wl[r*C_ + c] = l;
                if (c == 0) g_bias[r] = (r < 32) ? sem_b[r] : 0.f;
            }
        } else {
            int r0 = 160 + (blk-10)*8;
            __shared__ float fw[8*256];
            #pragma unroll
            for (int it = 0; it < 8; it++) {
                int e = tid + it*256;
                fw[e] = fuse_w[(r0-160)*C_ + e];
            }
            __syncthreads();
            float acc[8] = {};
            for (int m = 0; m < C_; m++) {
                float v = v_w[m*C_ + tid];
                #pragma unroll
                for (int rr = 0; rr < 8; rr++) acc[rr] += fw[rr*256 + m] * v;
            }
            #pragma unroll
            for (int rr = 0; rr < 8; rr++) {
                int r = r0 + rr;
                __nv_bfloat16 h, l; split_bf16(acc[rr], h, l);
                g_Wh[r*C_ + tid] = h; g_Wl[r*C_ + tid] = l;
                if (tid == 0) g_bias[r] = 0.f;
            }
        }
    } else {
        int w = (bx - 1066)*256 + tid;          // 48*256 = 12288
        ((uint*)g_Wh)[53248 + w] = 0;
        ((uint*)g_Wl)[53248 + w] = 0;
        if (w < 4096) ((float*)g_RK)[w] = 0.f;
        if (w < 8192) { g_RFV[w] = 0.f; g_RFV[w + 8192] = 0.f; }
        if (w < B_*K_) g_cnt[w] = 0;
    }
}

// ----------------------------- k_gemm (3-stage cp.async + ldmatrix; fused transpose + sem epilogue) ---
__device__ __forceinline__ void mma16816(float* d, const uint* a, uint b0, uint b1) {
    asm volatile(
        "mma.sync.aligned.m16n8k16.row.col.f32.bf16.bf16.f32 "
        "{%0,%1,%2,%3}, {%4,%5,%6,%7}, {%8,%9}, {%0,%1,%2,%3};"
        : "+f"(d[0]), "+f"(d[1]), "+f"(d[2]), "+f"(d[3])
        : "r"(a[0]), "r"(a[1]), "r"(a[2]), "r"(a[3]), "r"(b0), "r"(b1));
}
__device__ __forceinline__ void ldsm4(uint* r, uint addr) {
    asm volatile("ldmatrix.sync.aligned.m8n8.x4.shared.b16 {%0,%1,%2,%3}, [%4];"
        : "=r"(r[0]), "=r"(r[1]), "=r"(r[2]), "=r"(r[3]) : "r"(addr));
}
__device__ __forceinline__ void ldsm4t(uint* r, uint addr) {
    asm volatile("ldmatrix.sync.aligned.m8n8.x4.trans.shared.b16 {%0,%1,%2,%3}, [%4];"
        : "=r"(r[0]), "=r"(r[1]), "=r"(r[2]), "=r"(r[3]) : "r"(addr));
}
__device__ __forceinline__ void cpa16(uint dst, const void* src) {
    asm volatile("cp.async.cg.shared.global [%0], [%1], 16;" :: "r"(dst), "l"(src));
}

#define A_ST_BYTES (128*40*2)
#define B_ST_BYTES (32*136*2)
#define SB_BASE_OFF (6*A_ST_BYTES)
#define GEMM_SMEM (6*A_ST_BYTES + 6*B_ST_BYTES)

__device__ __forceinline__ void gemm_load(int st, int kc, int r0, int n0,
                                          const __nv_bfloat16* xh, const __nv_bfloat16* xl,
                                          uint sa_base, uint sb_base, int tid) {
    #pragma unroll
    for (int i = 0; i < 4; i++) {
        int ch = tid + i*256;
        int hl = ch >> 9, rem = ch & 511;
        int r = rem >> 2, c = (rem & 3)*8;
        const __nv_bfloat16* src = (hl ? g_Wl : g_Wh) + (r0 + r)*C_ + kc + c;
        cpa16(sa_base + (st*2 + hl)*A_ST_BYTES + (r*40 + c)*2, src);
    }
    #pragma unroll
    for (int i = 0; i < 4; i++) {
        int ch = tid + i*256;
        int hl = ch >> 9, rem = ch & 511;
        int k = rem >> 4, c = (rem & 15)*8;
        const __nv_bfloat16* src = (hl ? xl : xh) + (kc + k)*N_ + n0 + c;
        cpa16(sb_base + (st*2 + hl)*B_ST_BYTES + (k*136 + c)*2, src);
    }
    asm volatile("cp.async.commit_group;" ::: "memory");
}

__global__ void __launch_bounds__(256) k_gemm() {
    extern __shared__ __align__(16) char dsm[];
    uint sa_base = cvta_smem(dsm);
    uint sb_base = sa_base + SB_BASE_OFF;

    int n0 = blockIdx.x*128, r0 = blockIdx.y*128, b = blockIdx.z;
    int tid = threadIdx.x, lane = tid & 31, wid = tid >> 5;
    int wm = wid & 3, wn = wid >> 2;
    const __nv_bfloat16* xh = g_xh + b*C_*N_;
    const __nv_bfloat16* xl = g_xl + b*C_*N_;

    float acc[2][8][4];
    #pragma unroll
    for (int mt = 0; mt < 2; mt++)
        #pragma unroll
        for (int nt = 0; nt < 8; nt++)
            #pragma unroll
            for (int i = 0; i < 4; i++) acc[mt][nt][i] = 0.f;

    gemm_load(0, 0,  r0, n0, xh, xl, sa_base, sb_base, tid);
    gemm_load(1, 32, r0, n0, xh, xl, sa_base, sb_base, tid);

    for (int kt = 0; kt < 8; kt++) {
        if (kt < 7) asm volatile("cp.async.wait_group 1;" ::: "memory");
        else        asm volatile("cp.async.wait_group 0;" ::: "memory");
        __syncthreads();
        int st = kt % 3;
        uint sa0 = sa_base + (st*2+0)*A_ST_BYTES;
        uint sa1 = sa_base + (st*2+1)*A_ST_BYTES;
        uint sb0 = sb_base + (st*2+0)*B_ST_BYTES;
        uint sb1 = sb_base + (st*2+1)*B_ST_BYTES;
        #pragma unroll
        for (int k16 = 0; k16 < 2; k16++) {
            uint ah0[4], ah1[4], al0[4], al1[4];
            int ra = wm*32 + (lane & 15);
            int kcol = k16*16 + (lane >> 4)*8;
            ldsm4(ah0, sa0 + (ra*40 + kcol)*2);
            ldsm4(ah1, sa0 + ((ra+16)*40 + kcol)*2);
            ldsm4(al0, sa1 + (ra*40 + kcol)*2);
            ldsm4(al1, sa1 + ((ra+16)*40 + kcol)*2);
            int krow = k16*16 + (lane & 15);
            #pragma unroll
            for (int np = 0; np < 4; np++) {
                int nc = wn*64 + np*16 + (lane >> 4)*8;
                uint bh[4], bl[4];
                ldsm4t(bh, sb0 + (krow*136 + nc)*2);
                ldsm4t(bl, sb1 + (krow*136 + nc)*2);
                mma16816(acc[0][np*2],   ah0, bh[0], bh[1]);
                mma16816(acc[1][np*2],   ah1, bh[0], bh[1]);
                mma16816(acc[0][np*2+1], ah0, bh[2], bh[3]);
                mma16816(acc[1][np*2+1], ah1, bh[2], bh[3]);
                mma16816(acc[0][np*2],   ah0, bl[0], bl[1]);
                mma16816(acc[1][np*2],   ah1, bl[0], bl[1]);
                mma16816(acc[0][np*2+1], ah0, bl[2], bl[3]);
                mma16816(acc[1][np*2+1], ah1, bl[2], bl[3]);
                mma16816(acc[0][np*2],   al0, bh[0], bh[1]);
                mma16816(acc[1][np*2],   al1, bh[0], bh[1]);
                mma16816(acc[0][np*2+1], al0, bh[2], bh[3]);
                mma16816(acc[1][np*2+1], al1, bh[2], bh[3]);
            }
        }
        __syncthreads();
        if (kt + 2 < 8)
            gemm_load((kt+2) % 3, (kt+2)*32, r0, n0, xh, xl, sa_base, sb_base, tid);
    }

    // ---- epilogue: bias, P writes (rows >= 96 only), SMEM transpose for qT/kT/fvT ----
    float* T = (float*)dsm;                 // 128 x 133 floats
    #pragma unroll
    for (int mt = 0; mt < 2; mt++) {
        int rl = wm*32 + mt*16 + (lane >> 2);
        int r = r0 + rl;
        float bi0 = (r < R_) ? g_bias[r] : 0.f;
        float bi1 = (r + 8 < R_) ? g_bias[r + 8] : 0.f;
        #pragma unroll
        for (int nt = 0; nt < 8; nt++) {
            int nl = wn*64 + nt*8 + (lane & 3)*2;
            float v0 = acc[mt][nt][0] + bi0, v1 = acc[mt][nt][1] + bi0;
            float v2 = acc[mt][nt][2] + bi1, v3 = acc[mt][nt][3] + bi1;
            T[rl*133 + nl] = v0; T[rl*133 + nl + 1] = v1;
            T[(rl+8)*133 + nl] = v2; T[(rl+8)*133 + nl + 1] = v3;
            if (r >= 96 && r < R_)
                *(float2*)&g_P[(b*R_ + r)*N_ + n0 + nl] = make_float2(v0, v1);
            if (r + 8 >= 96 && r + 8 < R_)
                *(float2*)&g_P[(b*R_ + r + 8)*N_ + n0 + nl] = make_float2(v2, v3);
        }
    }
    __syncthreads();
    for (int i = 0; i < 64; i++) {
        int e = tid + i*256;
        int rl = e & 127, nl = e >> 7;
        int r = r0 + rl;
        if (r >= 32 && r < R_) {
            float v = T[rl*133 + nl];
            int n = n0 + nl;
            if (r < 96)       g_qT[(b*N_ + n)*D_ + (r - 32)]  = v;
            else if (r < 160) g_kT[(b*N_ + n)*D_ + (r - 96)]  = v;
            else              g_fvT[(b*N_ + n)*C_ + (r - 160)] = v;
        }
    }

    // ---- fused k_sem: r0==0 blocks hold sem rows 0..31 in T ----
    if (r0 == 0 && tid < 128) {
        int n = n0 + tid;
        float l[K_];
        float mx = -INFINITY; int am = 0;
        #pragma unroll
        for (int k = 0; k < K_; k++) {
            l[k] = T[k*133 + tid];
            if (l[k] > mx) { mx = l[k]; am = k; }
        }
        float sum = 0.f;
        #pragma unroll
        for (int k = 0; k < K_; k++) { l[k] = expf(l[k] - mx); sum += l[k]; }
        float inv = 1.f/sum;
        #pragma unroll
        for (int k = 0; k < K_; k++) g_sem[(b*K_ + k)*N_ + n] = l[k]*inv;
        int slot = atomicAdd(&g_cnt[b*K_ + am], 1);
        g_plist[(b*K_+am)*N_ + slot] = n;
    }
}

// ----------------------------- k_region (sp=16, 4 n-chunks) -----------------------------
__global__ void __launch_bounds__(256) k_region() {
    __shared__ float ss[32*68];
    __shared__ float ps[64*68];
    int ct = blockIdx.x, sp = blockIdx.y, b = blockIdx.z;
    int tid = threadIdx.x;
    int kk = tid & 31, cg = tid >> 5;
    float acc[8] = {};
    for (int nch = 0; nch < 4; nch++) {
        int nn0 = sp*256 + nch*64;
        #pragma unroll
        for (int i = 0; i < 8; i++) {
            int e = tid + i*256; int kr = e >> 6, nn = e & 63;
            ss[kr*68+nn] = g_sem[(b*K_+kr)*N_ + nn0 + nn];
        }
        #pragma unroll
        for (int i = 0; i < 16; i++) {
            int e = tid + i*256; int c = e >> 6, nn = e & 63;
            ps[c*68+nn] = g_P[(b*R_ + 96 + ct*64 + c)*N_ + nn0 + nn];
        }
        __syncthreads();
        #pragma unroll 4
        for (int nn = 0; nn < 64; nn += 4) {
            float4 sv = *(const float4*)&ss[kk*68 + nn];
            #pragma unroll
            for (int j = 0; j < 8; j++) {
                float4 pv = *(const float4*)&ps[(cg*8+j)*68 + nn];
                acc[j] += sv.x*pv.x;
                acc[j] += sv.y*pv.y;
                acc[j] += sv.z*pv.z;
                acc[j] += sv.w*pv.w;
            }
        }
        __syncthreads();
    }
    #pragma unroll
    for (int j = 0; j < 8; j++) {
        int o = ct*64 + cg*8 + j;
        if (o < 64) atomicAdd(&g_RK[(b*K_+kk)*D_ + o], acc[j]);
        else        atomicAdd(&g_RFV[(b*K_+kk)*C_ + (o-64)], acc[j]);
    }
}

// ----------------------------- k_sel -----------------------------
__global__ void __launch_bounds__(512) k_sel() {
    __shared__ ull cand[4096];
    __shared__ ull win[256];
    __shared__ int sufc[256];
    __shared__ int s_tc, s_cA, s_t, s_A, s_nw, s_nc;
    unsigned* hist = (unsigned*)cand;

    int bk = blockIdx.x; int b = bk >> 5, k = bk & 31;
    int tid = threadIdx.x;
    const float* row = g_sem + (b*K_ + k)*N_;

    for (int i = tid; i < 4096; i += 512) hist[i] = 0;
    __syncthreads();

    unsigned vb[8];
    #pragma unroll
    for (int j = 0; j < 8; j++) {
        vb[j] = __float_as_uint(row[tid + j*512]);
        atomicAdd(&hist[vb[j] >> 20], 1);
    }
    __syncthreads();

    if (tid < 256) {
        int cs = 0;
        #pragma unroll
        for (int h = 0; h < 16; h++) cs += hist[tid*16 + h];
        sufc[tid] = cs;
    }
    __syncthreads();
    #pragma unroll
    for (int st = 1; st < 256; st <<= 1) {
        int add = (tid < 256 && tid + st < 256) ? sufc[tid + st] : 0;
        __syncthreads();
        if (tid < 256) sufc[tid] += add;
        __syncthreads();
    }
    if (tid < 256) {
        int nxt = (tid < 255) ? sufc[tid + 1] : 0;
        if (sufc[tid] >= M_ && nxt < M_) { s_tc = tid; s_cA = nxt; }
    }
    if (tid == 0) { s_nw = 0; s_nc = 0; }
    __syncthreads();
    int tc = s_tc, cA = s_cA;
    if (tid < 16) {
        int sg = 0;
        for (int j = tid; j < 16; j++) sg += hist[tc*16 + j];
        int hi = hist[tc*16 + tid];
        if (cA + sg >= M_ && cA + sg - hi < M_) { s_t = tc*16 + tid; s_A = cA + sg - hi; }
    }
    __syncthreads();
    int t = s_t, A = s_A, s = M_ - A;
    __syncthreads();

    #pragma unroll
    for (int j = 0; j < 8; j++) {
        unsigned v = vb[j];
        int idx = tid + j*512;
        unsigned bkt = v >> 20;
        ull key = ((ull)v << 32) | (unsigned)(0xFFFFFFFFu - (unsigned)idx);
        if ((int)bkt > t) { int p = atomicAdd(&s_nw, 1); win[p] = ~key; }
        else if ((int)bkt == t) { int p = atomicAdd(&s_nc, 1); cand[p] = ~key; }
    }
    __syncthreads();

    int nc = s_nc;
    int P = 1; while (P < nc) P <<= 1;
    for (int i = tid; i < P; i += 512) if (i >= nc) cand[i] = 0xFFFFFFFFFFFFFFFFULL;
    __syncthreads();
    for (int sz = 2; sz <= P; sz <<= 1) {
        for (int str = sz >> 1; str > 0; str >>= 1) {
            for (int i = tid; i < P; i += 512) {
                int l = i ^ str;
                if (l > i) {
                    ull a = cand[i], c2 = cand[l];
                    bool up = ((i & sz) == 0);
                    if ((a > c2) == up) { cand[i] = c2; cand[l] = a; }
                }
            }
            __syncthreads();
        }
    }
    for (int i = tid; i < s; i += 512) win[A + i] = cand[i];
    __syncthreads();
    for (int sz = 2; sz <= 256; sz <<= 1) {
        for (int str = sz >> 1; str > 0; str >>= 1) {
            if (tid < 256) {
                int i = tid, l = i ^ str;
                if (l > i) {
                    ull a = win[i], c2 = win[l];
                    bool up = ((i & sz) == 0);
                    if ((a > c2) == up) { win[i] = c2; win[l] = a; }
                }
            }
            __syncthreads();
        }
    }
    if (tid < 256) g_ti[(b*K_ + k)*M_ + tid] = (int)(unsigned)(win[tid] & 0xFFFFFFFFu);
}

// ----------------------------- k_transpO -----------------------------
__global__ void k_transpO(float* __restrict__ out) {
    __shared__ float t[32][33];
    int b = blockIdx.z, c0 = blockIdx.x*32, n0 = blockIdx.y*32;
    int tx = threadIdx.x, ty = threadIdx.y;
    #pragma unroll
    for (int i = 0; i < 32; i += 8)
        t[ty+i][tx] = g_outT[b*N_*C_ + (n0 + ty + i)*C_ + c0 + tx];
    __syncthreads();
    #pragma unroll
    for (int i = 0; i < 32; i += 8)
        out[b*C_*N_ + (c0 + ty + i)*N_ + n0 + tx] = t[tx][ty+i];
}

// ----------------------------- k_main (chunk=32, pairwise-interleaved top-8) -----------------------------
#define MCH 32
__global__ void __launch_bounds__(256) k_main(const float* __restrict__ alpha_p,
                                              const float* __restrict__ fuse_b,
                                              const float* __restrict__ ln_g,
                                              const float* __restrict__ ln_b) {
    extern __shared__ float sm[];
    float* s_pkT = sm;                         // 64*257
    float* s_rfv = s_pkT + 64*257;             // 32*256
    float* s_rk  = s_rfv + 32*256;             // 32*65
    int*   s_pool= (int*)(s_rk + 32*65);       // 256

    int reg = blockIdx.y, b = blockIdx.z;
    int cnt = g_cnt[b*K_ + reg];
    if ((int)blockIdx.x * 32 >= cnt) return;
    int tid = threadIdx.x, lane = tid & 31, w = tid >> 5;

    if (tid < M_) s_pool[tid] = g_ti[(b*K_+reg)*M_ + tid];
    __syncthreads();
    #pragma unroll 4
    for (int i = 0; i < 64; i++) {
        int e = tid + i*256;
        int m = e >> 6, d = e & 63;
        s_pkT[d*257 + m] = g_kT[(b*N_ + s_pool[m])*D_ + d];
    }
    #pragma unroll
    for (int i = 0; i < 32; i++) s_rfv[tid + i*256] = g_RFV[b*K_*C_ + tid + i*256];
    #pragma unroll
    for (int i = 0; i < 8; i++) {
        int e = tid + i*256; int kk = e >> 6, d = e & 63;
        s_rk[kk*65+d] = g_RK[(b*K_+kk)*D_ + d];
    }
    __syncthreads();

    float a = 1.f/(1.f + expf(-alpha_p[0]));
    float one_a = 1.f - a;

    for (int chunk = blockIdx.x; chunk*32 < cnt; chunk += MCH) {
        int base = chunk*32;
        int pend = min(base+32, cnt);
        int p0 = base + w*4;
        if (p0 >= pend) continue;
        int nv = min(4, pend - p0);
        int n[4]; float q0[4], q1[4];
        #pragma unroll
        for (int i = 0; i < 4; i++) {
            if (i < nv) {
                n[i] = g_plist[(b*K_+reg)*N_ + p0 + i];
                q0[i] = g_qT[(b*N_+n[i])*D_ + lane];
                q1[i] = g_qT[(b*N_+n[i])*D_ + 32 + lane];
            } else { n[i] = 0; q0[i] = 0.f; q1[i] = 0.f; }
        }

        // sims[i][mi] over the 256-entry pool; lane owns m = mi*32+lane
        float sims[4][8] = {};
        #pragma unroll
        for (int dh = 0; dh < 2; dh++) {
            #pragma unroll 2
            for (int dd = 0; dd < 32; dd++) {
                const float* rowp = s_pkT + (dh*32+dd)*257;
                float r8[8];
                #pragma unroll
                for (int mi = 0; mi < 8; mi++) r8[mi] = rowp[mi*32 + lane];
                #pragma unroll
                for (int i = 0; i < 4; i++) {
                    float qd = __shfl_sync(0xFFFFFFFFu, dh ? q1[i] : q0[i], dd);
                    #pragma unroll
                    for (int mi = 0; mi < 8; mi++) sims[i][mi] += qd * r8[mi];
                }
            }
        }
        #pragma unroll
        for (int i = 0; i < 4; i++)
            #pragma unroll
            for (int mi = 0; mi < 8; mi++) sims[i][mi] *= INVSCALE;

        // pairwise-interleaved top-8 + softmax + sparse gather into cb
        float cb[4][8];
        #pragma unroll
        for (int ip = 0; ip < 2; ip++) {
            int i0 = ip*2, i1 = ip*2 + 1;
            float tv[2][8]; int tm[2][8];
            unsigned u0 = 0, u1 = 0;
            #pragma unroll
            for (int t = 0; t < 8; t++) {
                float bv0 = -INFINITY, bv1 = -INFINITY;
                int bm0 = 1 << 30, bm1 = 1 << 30;
                #pragma unroll
                for (int mi = 0; mi < 8; mi++) {
                    int m = mi*32 + lane;
                    if (!(u0 & (1u << mi))) {
                        float v = sims[i0][mi];
                        if (v > bv0 || (v == bv0 && m < bm0)) { bv0 = v; bm0 = m; }
                    }
                    if (!(u1 & (1u << mi))) {
                        float v = sims[i1][mi];
                        if (v > bv1 || (v == bv1 && m < bm1)) { bv1 = v; bm1 = m; }
                    }
                }
                #pragma unroll
                for (int off = 16; off > 0; off >>= 1) {
                    float ov0 = __shfl_xor_sync(0xFFFFFFFFu, bv0, off);
                    int   om0 = __shfl_xor_sync(0xFFFFFFFFu, bm0, off);
                    float ov1 = __shfl_xor_sync(0xFFFFFFFFu, bv1, off);
                    int   om1 = __shfl_xor_sync(0xFFFFFFFFu, bm1, off);
                    if (ov0 > bv0 || (ov0 == bv0 && om0 < bm0)) { bv0 = ov0; bm0 = om0; }
                    if (ov1 > bv1 || (ov1 == bv1 && om1 < bm1)) { bv1 = ov1; bm1 = om1; }
                }
                tv[0][t] = bv0; tm[0][t] = bm0;
                tv[1][t] = bv1; tm[1][t] = bm1;
                if ((bm0 & 31) == lane) u0 |= 1u << (bm0 >> 5);
                if ((bm1 & 31) == lane) u1 |= 1u << (bm1 >> 5);
            }
            // softmax + gather (pair interleaved at the load level via unroll)
            #pragma unroll
            for (int s2 = 0; s2 < 2; s2++) {
                int ii = ip*2 + s2;
                float ww[8], wsum = 0.f;
                #pragma unroll
                for (int t = 0; t < 8; t++) { ww[t] = expf(tv[s2][t] - tv[s2][0]); wsum += ww[t]; }
                float winv = one_a/wsum;
                float fs[8] = {};
                #pragma unroll
                for (int t = 0; t < 8; t++) {
                    float att = ww[t]*winv;
                    int gidx = s_pool[tm[s2][t]];
                    const float* fvrow = g_fvT + (b*N_ + gidx)*C_;
                    #pragma unroll
                    for (int j = 0; j < 8; j++) fs[j] += att * fvrow[j*32 + lane];
                }
                #pragma unroll
                for (int j = 0; j < 8; j++) cb[ii][j] = fs[j];
            }
        }

        // batched dense logits: lg[i][k=lane] = q_i . rk[lane]
        float lg[4] = {0.f, 0.f, 0.f, 0.f};
        #pragma unroll
        for (int dh = 0; dh < 2; dh++) {
            #pragma unroll 4
            for (int dd = 0; dd < 32; dd++) {
                float rkv = s_rk[lane*65 + dh*32 + dd];
                #pragma unroll
                for (int i = 0; i < 4; i++) {
                    float qd = __shfl_sync(0xFFFFFFFFu, dh ? q1[i] : q0[i], dd);
                    lg[i] += qd * rkv;
                }
            }
        }
        float mx[4], es[4], aat[4];
        #pragma unroll
        for (int i = 0; i < 4; i++) { lg[i] *= INVSCALE; mx[i] = lg[i]; }
        #pragma unroll
        for (int off = 16; off > 0; off >>= 1) {
            #pragma unroll
            for (int i = 0; i < 4; i++)
                mx[i] = fmaxf(mx[i], __shfl_xor_sync(0xFFFFFFFFu, mx[i], off));
        }
        #pragma unroll
        for (int i = 0; i < 4; i++) { aat[i] = expf(lg[i] - mx[i]); es[i] = aat[i]; }
        #pragma unroll
        for (int off = 16; off > 0; off >>= 1) {
            #pragma unroll
            for (int i = 0; i < 4; i++)
                es[i] += __shfl_xor_sync(0xFFFFFFFFu, es[i], off);
        }
        #pragma unroll
        for (int i = 0; i < 4; i++) aat[i] = a*aat[i]/es[i];

        // batched fc accumulate into cb (4x SMEM reuse)
        #pragma unroll 4
        for (int kk = 0; kk < K_; kk++) {
            const float* rrow = s_rfv + kk*256;
            float r8[8];
            #pragma unroll
            for (int j = 0; j < 8; j++) r8[j] = rrow[j*32 + lane];
            #pragma unroll
            for (int i = 0; i < 4; i++) {
                float ak = __shfl_sync(0xFFFFFFFFu, aat[i], kk);
                #pragma unroll
                for (int j = 0; j < 8; j++) cb[i][j] += ak * r8[j];
            }
        }

        // per-position epilogue: bias + residual + channel LN
        #pragma unroll 1
        for (int i = 0; i < 4; i++) {
            if (i >= nv) break;
            float pre[8], sum = 0.f, sq = 0.f;
            const float* xrow = g_xT + (b*N_+n[i])*C_;
            #pragma unroll
            for (int j = 0; j < 8; j++) {
                int c = j*32 + lane;
                float v = xrow[c] + cb[i][j] + fuse_b[c];
                pre[j] = v; sum += v; sq += v*v;
            }
            #pragma unroll
            for (int off = 16; off > 0; off >>= 1) {
                sum += __shfl_xor_sync(0xFFFFFFFFu, sum, off);
                sq  += __shfl_xor_sync(0xFFFFFFFFu, sq,  off);
            }
            float mu = sum * (1.f/256.f);
            float var = sq * (1.f/256.f) - mu*mu;
            float rstd = rsqrtf(var + 1e-5f);
            float* orow = g_outT + (b*N_+n[i])*C_;
            #pragma unroll
            for (int j = 0; j < 8; j++) {
                int c = j*32 + lane;
                orow[c] = (pre[j]-mu)*rstd*ln_g[c] + ln_b[c];
            }
        }
    }
}

// ----------------------------- launch -----------------------------
extern "C" void kernel_launch(void* const* d_in, const int* in_sizes, int n_in,
                              void* d_out, int out_size) {
    const float* x      = (const float*)d_in[0];
    const float* sem_w  = (const float*)d_in[1];
    const float* sem_b  = (const float*)d_in[2];
    const float* q_w    = (const float*)d_in[3];
    const float* k_w    = (const float*)d_in[4];
    const float* v_w    = (const float*)d_in[5];
    const float* fuse_w = (const float*)d_in[6];
    const float* fuse_b = (const float*)d_in[7];
    const float* alpha  = (const float*)d_in[8];
    const float* ln_g   = (const float*)d_in[9];
    const float* ln_b   = (const float*)d_in[10];
    float* out = (float*)d_out;

    const int SMEM_MAIN = (64*257 + 32*256 + 32*65)*4 + 256*4;
    cudaFuncSetAttribute((const void*)k_main,
                         cudaFuncAttributeMaxDynamicSharedMemorySize, SMEM_MAIN);
    cudaFuncSetAttribute((const void*)k_gemm,
                         cudaFuncAttributeMaxDynamicSharedMemorySize, GEMM_SMEM);

    k_pre<<<1114, 256>>>(x, sem_w, sem_b, q_w, k_w, v_w, fuse_w); // #1
    k_gemm<<<dim3(32, 4, B_), 256, GEMM_SMEM>>>();                // #2 (sem fused)
    k_region<<<dim3(5, 16, B_), 256>>>();                         // #3
    k_sel<<<B_*K_, 512>>>();                                      // #4  <- ncu slot
    k_main<<<dim3(MCH, K_, B_), 256, SMEM_MAIN>>>(alpha, fuse_b, ln_g, ln_b); // #5
    k_transpO<<<dim3(8, 128, B_), dim3(32, 8)>>>(out);            // #6
}

// round 15
// speedup vs baseline: 1.3752x; 1.0223x over previous
#include <cuda_runtime.h>
#include <cuda_bf16.h>
#include <math.h>

#define B_ 2
#define C_ 256
#define N_ 4096
#define D_ 64
#define K_ 32
#define M_ 256
#define R_ 416
#define RP2 512
#define INVSCALE (1.0f/8.000001f)
typedef unsigned long long ull;
typedef unsigned int uint;

// ----------------------------- scratch -----------------------------
__device__ __align__(16) __nv_bfloat16 g_Wh[RP2*C_];
__device__ __align__(16) __nv_bfloat16 g_Wl[RP2*C_];
__device__ __align__(16) __nv_bfloat16 g_xh[B_*C_*N_];
__device__ __align__(16) __nv_bfloat16 g_xl[B_*C_*N_];
__device__ float g_bias[R_];
__device__ float g_P[B_*R_*N_];        // rows 96..415 used: [k(64); fv(256)]
__device__ float g_sem[B_*K_*N_];
__device__ int   g_ti[B_*K_*M_];
__device__ int   g_cnt[B_*K_];
__device__ int   g_plist[B_*K_*N_];
__device__ float g_qT[B_*N_*D_];
__device__ float g_kT[B_*N_*D_];
__device__ float g_fvT[B_*N_*C_];
__device__ float g_xT[B_*N_*C_];
__device__ float g_RK[B_*K_*D_];
__device__ float g_RFV[B_*K_*C_];
__device__ float g_outT[B_*N_*C_];

__device__ __forceinline__ void split_bf16(float v, __nv_bfloat16& h, __nv_bfloat16& l) {
    h = __float2bfloat16_rn(v);
    l = __float2bfloat16_rn(v - __bfloat162float(h));
}
__device__ __forceinline__ uint cvta_smem(const void* p) {
    return (uint)__cvta_generic_to_shared(p);
}

// ----------------------------- k_pre (fused zero + cvtx + prep) -----------------------------
__global__ void __launch_bounds__(256) k_pre(
    const float* __restrict__ x,
    const float* __restrict__ sem_w, const float* __restrict__ sem_b,
    const float* __restrict__ q_w,  const float* __restrict__ k_w,
    const float* __restrict__ v_w,  const float* __restrict__ fuse_w) {
    int bx = blockIdx.x, tid = threadIdx.x;
    if (bx < 1024) {
        __shared__ float t[64][33];
        int n0 = (bx & 63)*64, c0 = ((bx >> 6) & 7)*32, b = bx >> 9;
        int tx = tid & 31, ty = tid >> 5;
        #pragma unroll
        for (int i = 0; i < 4; i++) {
            int c = c0 + ty + i*8;
            int n = n0 + tx*2;
            float2 v = *(const float2*)&x[(b*C_ + c)*N_ + n];
            __nv_bfloat16 h0, l0, h1, l1;
            split_bf16(v.x, h0, l0); split_bf16(v.y, h1, l1);
            uint hw = (uint)__bfloat16_as_ushort(h0) | ((uint)__bfloat16_as_ushort(h1) << 16);
            uint lw = (uint)__bfloat16_as_ushort(l0) | ((uint)__bfloat16_as_ushort(l1) << 16);
            *(uint*)&g_xh[(b*C_ + c)*N_ + n] = hw;
            *(uint*)&g_xl[(b*C_ + c)*N_ + n] = lw;
            t[tx*2][ty + i*8]     = v.x;
            t[tx*2 + 1][ty + i*8] = v.y;
        }
        __syncthreads();
        #pragma unroll
        for (int i = 0; i < 8; i++) {
            int nn = ty + i*8;
            g_xT[(b*N_ + n0 + nn)*C_ + c0 + tx] = t[nn][tx];
        }
    } else if (bx < 1066) {
        int blk = bx - 1024;
        if (blk < 10) {
            #pragma unroll
            for (int it = 0; it < 16; it++) {
                int e = tid + it*256;
                int r = blk*16 + (e >> 8), c = e & 255;
                float val = (r < 32) ? sem_w[r*C_ + c]
                          : (r < 96) ? q_w[(r-32)*C_ + c]
                                     : k_w[(r-96)*C_ + c];
                __nv_bfloat16 h, l; split_bf16(val, h, l);
                g_Wh[r*C_ + c] = h; g_Wl[r*C_ + c] = l;
                if (c == 0) g_bias[r] = (r < 32) ? sem_b[r] : 0.f;
            }
        } else {
            int r0 = 160 + (blk-10)*8;
            __shared__ float fw[8*256];
            #pragma unroll
            for (int it = 0; it < 8; it++) {
                int e = tid + it*256;
                fw[e] = fuse_w[(r0-160)*C_ + e];
            }
            __syncthreads();
            float acc[8] = {};
            for (int m = 0; m < C_; m++) {
                float v = v_w[m*C_ + tid];
                #pragma unroll
                for (int rr = 0; rr < 8; rr++) acc[rr] += fw[rr*256 + m] * v;
            }
            #pragma unroll
            for (int rr = 0; rr < 8; rr++) {
                int r = r0 + rr;
                __nv_bfloat16 h, l; split_bf16(acc[rr], h, l);
                g_Wh[r*C_ + tid] = h; g_Wl[r*C_ + tid] = l;
                if (tid == 0) g_bias[r] = 0.f;
            }
        }
    } else {
        int w = (bx - 1066)*256 + tid;
        ((uint*)g_Wh)[53248 + w] = 0;
        ((uint*)g_Wl)[53248 + w] = 0;
        if (w < 4096) ((float*)g_RK)[w] = 0.f;
        if (w < 8192) { g_RFV[w] = 0.f; g_RFV[w + 8192] = 0.f; }
        if (w < B_*K_) g_cnt[w] = 0;
    }
}

// ----------------------------- k_gemm (3-stage cp.async + ldmatrix; fused transpose + sem epilogue) ---
__device__ __forceinline__ void mma16816(float* d, const uint* a, uint b0, uint b1) {
    asm volatile(
        "mma.sync.aligned.m16n8k16.row.col.f32.bf16.bf16.f32 "
        "{%0,%1,%2,%3}, {%4,%5,%6,%7}, {%8,%9}, {%0,%1,%2,%3};"
        : "+f"(d[0]), "+f"(d[1]), "+f"(d[2]), "+f"(d[3])
        : "r"(a[0]), "r"(a[1]), "r"(a[2]), "r"(a[3]), "r"(b0), "r"(b1));
}
__device__ __forceinline__ void ldsm4(uint* r, uint addr) {
    asm volatile("ldmatrix.sync.aligned.m8n8.x4.shared.b16 {%0,%1,%2,%3}, [%4];"
        : "=r"(r[0]), "=r"(r[1]), "=r"(r[2]), "=r"(r[3]) : "r"(addr));
}
__device__ __forceinline__ void ldsm4t(uint* r, uint addr) {
    asm volatile("ldmatrix.sync.aligned.m8n8.x4.trans.shared.b16 {%0,%1,%2,%3}, [%4];"
        : "=r"(r[0]), "=r"(r[1]), "=r"(r[2]), "=r"(r[3]) : "r"(addr));
}
__device__ __forceinline__ void cpa16(uint dst, const void* src) {
    asm volatile("cp.async.cg.shared.global [%0], [%1], 16;" :: "r"(dst), "l"(src));
}

#define A_ST_BYTES (128*40*2)
#define B_ST_BYTES (32*136*2)
#define SB_BASE_OFF (6*A_ST_BYTES)
#define GEMM_SMEM (6*A_ST_BYTES + 6*B_ST_BYTES)

__device__ __forceinline__ void gemm_load(int st, int kc, int r0, int n0,
                                          const __nv_bfloat16* xh, const __nv_bfloat16* xl,
                                          uint sa_base, uint sb_base, int tid) {
    #pragma unroll
    for (int i = 0; i < 4; i++) {
        int ch = tid + i*256;
        int hl = ch >> 9, rem = ch & 511;
        int r = rem >> 2, c = (rem & 3)*8;
        const __nv_bfloat16* src = (hl ? g_Wl : g_Wh) + (r0 + r)*C_ + kc + c;
        cpa16(sa_base + (st*2 + hl)*A_ST_BYTES + (r*40 + c)*2, src);
    }
    #pragma unroll
    for (int i = 0; i < 4; i++) {
        int ch = tid + i*256;
        int hl = ch >> 9, rem = ch & 511;
        int k = rem >> 4, c = (rem & 15)*8;
        const __nv_bfloat16* src = (hl ? xl : xh) + (kc + k)*N_ + n0 + c;
        cpa16(sb_base + (st*2 + hl)*B_ST_BYTES + (k*136 + c)*2, src);
    }
    asm volatile("cp.async.commit_group;" ::: "memory");
}

__global__ void __launch_bounds__(256) k_gemm() {
    extern __shared__ __align__(16) char dsm[];
    uint sa_base = cvta_smem(dsm);
    uint sb_base = sa_base + SB_BASE_OFF;

    int n0 = blockIdx.x*128, r0 = blockIdx.y*128, b = blockIdx.z;
    int tid = threadIdx.x, lane = tid & 31, wid = tid >> 5;
    int wm = wid & 3, wn = wid >> 2;
    const __nv_bfloat16* xh = g_xh + b*C_*N_;
    const __nv_bfloat16* xl = g_xl + b*C_*N_;

    float acc[2][8][4];
    #pragma unroll
    for (int mt = 0; mt < 2; mt++)
        #pragma unroll
        for (int nt = 0; nt < 8; nt++)
            #pragma unroll
            for (int i = 0; i < 4; i++) acc[mt][nt][i] = 0.f;

    gemm_load(0, 0,  r0, n0, xh, xl, sa_base, sb_base, tid);
    gemm_load(1, 32, r0, n0, xh, xl, sa_base, sb_base, tid);

    for (int kt = 0; kt < 8; kt++) {
        if (kt < 7) asm volatile("cp.async.wait_group 1;" ::: "memory");
        else        asm volatile("cp.async.wait_group 0;" ::: "memory");
        __syncthreads();
        int st = kt % 3;
        uint sa0 = sa_base + (st*2+0)*A_ST_BYTES;
        uint sa1 = sa_base + (st*2+1)*A_ST_BYTES;
        uint sb0 = sb_base + (st*2+0)*B_ST_BYTES;
        uint sb1 = sb_base + (st*2+1)*B_ST_BYTES;
        #pragma unroll
        for (int k16 = 0; k16 < 2; k16++) {
            uint ah0[4], ah1[4], al0[4], al1[4];
            int ra = wm*32 + (lane & 15);
            int kcol = k16*16 + (lane >> 4)*8;
            ldsm4(ah0, sa0 + (ra*40 + kcol)*2);
            ldsm4(ah1, sa0 + ((ra+16)*40 + kcol)*2);
            ldsm4(al0, sa1 + (ra*40 + kcol)*2);
            ldsm4(al1, sa1 + ((ra+16)*40 + kcol)*2);
            int krow = k16*16 + (lane & 15);
            #pragma unroll
            for (int np = 0; np < 4; np++) {
                int nc = wn*64 + np*16 + (lane >> 4)*8;
                uint bh[4], bl[4];
                ldsm4t(bh, sb0 + (krow*136 + nc)*2);
                ldsm4t(bl, sb1 + (krow*136 + nc)*2);
                mma16816(acc[0][np*2],   ah0, bh[0], bh[1]);
                mma16816(acc[1][np*2],   ah1, bh[0], bh[1]);
                mma16816(acc[0][np*2+1], ah0, bh[2], bh[3]);
                mma16816(acc[1][np*2+1], ah1, bh[2], bh[3]);
                mma16816(acc[0][np*2],   ah0, bl[0], bl[1]);
                mma16816(acc[1][np*2],   ah1, bl[0], bl[1]);
                mma16816(acc[0][np*2+1], ah0, bl[2], bl[3]);
                mma16816(acc[1][np*2+1], ah1, bl[2], bl[3]);
                mma16816(acc[0][np*2],   al0, bh[0], bh[1]);
                mma16816(acc[1][np*2],   al1, bh[0], bh[1]);
                mma16816(acc[0][np*2+1], al0, bh[2], bh[3]);
                mma16816(acc[1][np*2+1], al1, bh[2], bh[3]);
            }
        }
        __syncthreads();
        if (kt + 2 < 8)
            gemm_load((kt+2) % 3, (kt+2)*32, r0, n0, xh, xl, sa_base, sb_base, tid);
    }

    // ---- epilogue: bias, P writes (rows >= 96 only), SMEM transpose for qT/kT/fvT ----
    float* T = (float*)dsm;                 // 128 x 133 floats
    #pragma unroll
    for (int mt = 0; mt < 2; mt++) {
        int rl = wm*32 + mt*16 + (lane >> 2);
        int r = r0 + rl;
        float bi0 = (r < R_) ? g_bias[r] : 0.f;
        float bi1 = (r + 8 < R_) ? g_bias[r + 8] : 0.f;
        #pragma unroll
        for (int nt = 0; nt < 8; nt++) {
            int nl = wn*64 + nt*8 + (lane & 3)*2;
            float v0 = acc[mt][nt][0] + bi0, v1 = acc[mt][nt][1] + bi0;
            float v2 = acc[mt][nt][2] + bi1, v3 = acc[mt][nt][3] + bi1;
            T[rl*133 + nl] = v0; T[rl*133 + nl + 1] = v1;
            T[(rl+8)*133 + nl] = v2; T[(rl+8)*133 + nl + 1] = v3;
            if (r >= 96 && r < R_)
                *(float2*)&g_P[(b*R_ + r)*N_ + n0 + nl] = make_float2(v0, v1);
            if (r + 8 >= 96 && r + 8 < R_)
                *(float2*)&g_P[(b*R_ + r + 8)*N_ + n0 + nl] = make_float2(v2, v3);
        }
    }
    __syncthreads();
    for (int i = 0; i < 64; i++) {
        int e = tid + i*256;
        int rl = e & 127, nl = e >> 7;
        int r = r0 + rl;
        if (r >= 32 && r < R_) {
            float v = T[rl*133 + nl];
            int n = n0 + nl;
            if (r < 96)       g_qT[(b*N_ + n)*D_ + (r - 32)]  = v;
            else if (r < 160) g_kT[(b*N_ + n)*D_ + (r - 96)]  = v;
            else              g_fvT[(b*N_ + n)*C_ + (r - 160)] = v;
        }
    }

    // ---- fused k_sem: r0==0 blocks hold sem rows 0..31 in T ----
    if (r0 == 0 && tid < 128) {
        int n = n0 + tid;
        float l[K_];
        float mx = -INFINITY; int am = 0;
        #pragma unroll
        for (int k = 0; k < K_; k++) {
            l[k] = T[k*133 + tid];
            if (l[k] > mx) { mx = l[k]; am = k; }
        }
        float sum = 0.f;
        #pragma unroll
        for (int k = 0; k < K_; k++) { l[k] = expf(l[k] - mx); sum += l[k]; }
        float inv = 1.f/sum;
        #pragma unroll
        for (int k = 0; k < K_; k++) g_sem[(b*K_ + k)*N_ + n] = l[k]*inv;
        int slot = atomicAdd(&g_cnt[b*K_ + am], 1);
        g_plist[(b*K_+am)*N_ + slot] = n;
    }
}

// ----------------------------- k_regsel (fused region + sel; 512 threads) -----------------------------
// blocks [0,160): region (ct=blk%5, sp=(blk/5)%16, b=blk/80)
// blocks [160,224): sel (b,k from blk-160)
__global__ void __launch_bounds__(512) k_regsel() {
    __shared__ __align__(16) char sbuf[36992];
    __shared__ int s_tc, s_cA, s_t, s_A, s_nw, s_nc;
    int blk = blockIdx.x, tid = threadIdx.x;

    if (blk < 160) {
        float* ss = (float*)sbuf;              // 32*68 floats
        float* ps = ss + 32*68;                // 64*68 floats
        int ct = blk % 5, sp = (blk/5) & 15, b = blk/80;
        int kk = tid & 31, cg = (tid >> 5) & 7, half = tid >> 8;
        int nnbase = half*32;
        float acc[8] = {};
        for (int nch = 0; nch < 4; nch++) {
            int nn0 = sp*256 + nch*64;
            #pragma unroll
            for (int i = 0; i < 4; i++) {
                int e = tid + i*512; int kr = e >> 6, nn = e & 63;
                ss[kr*68+nn] = g_sem[(b*K_+kr)*N_ + nn0 + nn];
            }
            #pragma unroll
            for (int i = 0; i < 8; i++) {
                int e = tid + i*512; int c = e >> 6, nn = e & 63;
                ps[c*68+nn] = g_P[(b*R_ + 96 + ct*64 + c)*N_ + nn0 + nn];
            }
            __syncthreads();
            #pragma unroll 4
            for (int nn = 0; nn < 32; nn += 4) {
                float4 sv = *(const float4*)&ss[kk*68 + nnbase + nn];
                #pragma unroll
                for (int j = 0; j < 8; j++) {
                    float4 pv = *(const float4*)&ps[(cg*8+j)*68 + nnbase + nn];
                    acc[j] += sv.x*pv.x;
                    acc[j] += sv.y*pv.y;
                    acc[j] += sv.z*pv.z;
                    acc[j] += sv.w*pv.w;
                }
            }
            __syncthreads();
        }
        #pragma unroll
        for (int j = 0; j < 8; j++) {
            int o = ct*64 + cg*8 + j;
            if (o < 64) atomicAdd(&g_RK[(b*K_+kk)*D_ + o], acc[j]);
            else        atomicAdd(&g_RFV[(b*K_+kk)*C_ + (o-64)], acc[j]);
        }
        return;
    }

    // ---- sel part ----
    ull* cand = (ull*)sbuf;                    // 4096
    ull* win  = cand + 4096;                   // 256
    int* sufc = (int*)(win + 256);             // 256
    unsigned* hist = (unsigned*)cand;

    int bk = blk - 160; int b = bk >> 5, k = bk & 31;
    const float* row = g_sem + (b*K_ + k)*N_;

    for (int i = tid; i < 4096; i += 512) hist[i] = 0;
    __syncthreads();

    unsigned vb[8];
    #pragma unroll
    for (int j = 0; j < 8; j++) {
        vb[j] = __float_as_uint(row[tid + j*512]);
        atomicAdd(&hist[vb[j] >> 20], 1);
    }
    __syncthreads();

    if (tid < 256) {
        int cs = 0;
        #pragma unroll
        for (int h = 0; h < 16; h++) cs += hist[tid*16 + h];
        sufc[tid] = cs;
    }
    __syncthreads();
    #pragma unroll
    for (int st = 1; st < 256; st <<= 1) {
        int add = (tid < 256 && tid + st < 256) ? sufc[tid + st] : 0;
        __syncthreads();
        if (tid < 256) sufc[tid] += add;
        __syncthreads();
    }
    if (tid < 256) {
        int nxt = (tid < 255) ? sufc[tid + 1] : 0;
        if (sufc[tid] >= M_ && nxt < M_) { s_tc = tid; s_cA = nxt; }
    }
    if (tid == 0) { s_nw = 0; s_nc = 0; }
    __syncthreads();
    int tc = s_tc, cA = s_cA;
    if (tid < 16) {
        int sg = 0;
        for (int j = tid; j < 16; j++) sg += hist[tc*16 + j];
        int hi = hist[tc*16 + tid];
        if (cA + sg >= M_ && cA + sg - hi < M_) { s_t = tc*16 + tid; s_A = cA + sg - hi; }
    }
    __syncthreads();
    int t = s_t, A = s_A, s = M_ - A;
    __syncthreads();

    #pragma unroll
    for (int j = 0; j < 8; j++) {
        unsigned v = vb[j];
        int idx = tid + j*512;
        unsigned bkt = v >> 20;
        ull key = ((ull)v << 32) | (unsigned)(0xFFFFFFFFu - (unsigned)idx);
        if ((int)bkt > t) { int p = atomicAdd(&s_nw, 1); win[p] = ~key; }
        else if ((int)bkt == t) { int p = atomicAdd(&s_nc, 1); cand[p] = ~key; }
    }
    __syncthreads();

    int nc = s_nc;
    int P = 1; while (P < nc) P <<= 1;
    for (int i = tid; i < P; i += 512) if (i >= nc) cand[i] = 0xFFFFFFFFFFFFFFFFULL;
    __syncthreads();
    for (int sz = 2; sz <= P; sz <<= 1) {
        for (int str = sz >> 1; str > 0; str >>= 1) {
            for (int i = tid; i < P; i += 512) {
                int l = i ^ str;
                if (l > i) {
                    ull a = cand[i], c2 = cand[l];
                    bool up = ((i & sz) == 0);
                    if ((a > c2) == up) { cand[i] = c2; cand[l] = a; }
                }
            }
            __syncthreads();
        }
    }
    for (int i = tid; i < s; i += 512) win[A + i] = cand[i];
    __syncthreads();
    for (int sz = 2; sz <= 256; sz <<= 1) {
        for (int str = sz >> 1; str > 0; str >>= 1) {
            if (tid < 256) {
                int i = tid, l = i ^ str;
                if (l > i) {
                    ull a = win[i], c2 = win[l];
                    bool up = ((i & sz) == 0);
                    if ((a > c2) == up) { win[i] = c2; win[l] = a; }
                }
            }
            __syncthreads();
        }
    }
    if (tid < 256) g_ti[(b*K_ + k)*M_ + tid] = (int)(unsigned)(win[tid] & 0xFFFFFFFFu);
}

// ----------------------------- k_transpO -----------------------------
__global__ void k_transpO(float* __restrict__ out) {
    __shared__ float t[32][33];
    int b = blockIdx.z, c0 = blockIdx.x*32, n0 = blockIdx.y*32;
    int tx = threadIdx.x, ty = threadIdx.y;
    #pragma unroll
    for (int i = 0; i < 32; i += 8)
        t[ty+i][tx] = g_outT[b*N_*C_ + (n0 + ty + i)*C_ + c0 + tx];
    __syncthreads();
    #pragma unroll
    for (int i = 0; i < 32; i += 8)
        out[b*C_*N_ + (c0 + ty + i)*N_ + n0 + tx] = t[tx][ty+i];
}

// ----------------------------- k_main (chunk=32, pairwise-interleaved top-8) -----------------------------
#define MCH 32
__global__ void __launch_bounds__(256) k_main(const float* __restrict__ alpha_p,
                                              const float* __restrict__ fuse_b,
                                              const float* __restrict__ ln_g,
                                              const float* __restrict__ ln_b) {
    extern __shared__ float sm[];
    float* s_pkT = sm;                         // 64*257
    float* s_rfv = s_pkT + 64*257;             // 32*256
    float* s_rk  = s_rfv + 32*256;             // 32*65
    int*   s_pool= (int*)(s_rk + 32*65);       // 256

    int reg = blockIdx.y, b = blockIdx.z;
    int cnt = g_cnt[b*K_ + reg];
    if ((int)blockIdx.x * 32 >= cnt) return;
    int tid = threadIdx.x, lane = tid & 31, w = tid >> 5;

    if (tid < M_) s_pool[tid] = g_ti[(b*K_+reg)*M_ + tid];
    __syncthreads();
    #pragma unroll 4
    for (int i = 0; i < 64; i++) {
        int e = tid + i*256;
        int m = e >> 6, d = e & 63;
        s_pkT[d*257 + m] = g_kT[(b*N_ + s_pool[m])*D_ + d];
    }
    #pragma unroll
    for (int i = 0; i < 32; i++) s_rfv[tid + i*256] = g_RFV[b*K_*C_ + tid + i*256];
    #pragma unroll
    for (int i = 0; i < 8; i++) {
        int e = tid + i*256; int kk = e >> 6, d = e & 63;
        s_rk[kk*65+d] = g_RK[(b*K_+kk)*D_ + d];
    }
    __syncthreads();

    float a = 1.f/(1.f + expf(-alpha_p[0]));
    float one_a = 1.f - a;

    for (int chunk = blockIdx.x; chunk*32 < cnt; chunk += MCH) {
        int base = chunk*32;
        int pend = min(base+32, cnt);
        int p0 = base + w*4;
        if (p0 >= pend) continue;
        int nv = min(4, pend - p0);
        int n[4]; float q0[4], q1[4];
        #pragma unroll
        for (int i = 0; i < 4; i++) {
            if (i < nv) {
                n[i] = g_plist[(b*K_+reg)*N_ + p0 + i];
                q0[i] = g_qT[(b*N_+n[i])*D_ + lane];
                q1[i] = g_qT[(b*N_+n[i])*D_ + 32 + lane];
            } else { n[i] = 0; q0[i] = 0.f; q1[i] = 0.f; }
        }

        float sims[4][8] = {};
        #pragma unroll
        for (int dh = 0; dh < 2; dh++) {
            #pragma unroll 2
            for (int dd = 0; dd < 32; dd++) {
                const float* rowp = s_pkT + (dh*32+dd)*257;
                float r8[8];
                #pragma unroll
                for (int mi = 0; mi < 8; mi++) r8[mi] = rowp[mi*32 + lane];
                #pragma unroll
                for (int i = 0; i < 4; i++) {
                    float qd = __shfl_sync(0xFFFFFFFFu, dh ? q1[i] : q0[i], dd);
                    #pragma unroll
                    for (int mi = 0; mi < 8; mi++) sims[i][mi] += qd * r8[mi];
                }
            }
        }
        #pragma unroll
        for (int i = 0; i < 4; i++)
            #pragma unroll
            for (int mi = 0; mi < 8; mi++) sims[i][mi] *= INVSCALE;

        float cb[4][8];
        #pragma unroll
        for (int ip = 0; ip < 2; ip++) {
            int i0 = ip*2, i1 = ip*2 + 1;
            float tv[2][8]; int tm[2][8];
            unsigned u0 = 0, u1 = 0;
            #pragma unroll
            for (int t = 0; t < 8; t++) {
                float bv0 = -INFINITY, bv1 = -INFINITY;
                int bm0 = 1 << 30, bm1 = 1 << 30;
                #pragma unroll
                for (int mi = 0; mi < 8; mi++) {
                    int m = mi*32 + lane;
                    if (!(u0 & (1u << mi))) {
                        float v = sims[i0][mi];
                        if (v > bv0 || (v == bv0 && m < bm0)) { bv0 = v; bm0 = m; }
                    }
                    if (!(u1 & (1u << mi))) {
                        float v = sims[i1][mi];
                        if (v > bv1 || (v == bv1 && m < bm1)) { bv1 = v; bm1 = m; }
                    }
                }
                #pragma unroll
                for (int off = 16; off > 0; off >>= 1) {
                    float ov0 = __shfl_xor_sync(0xFFFFFFFFu, bv0, off);
                    int   om0 = __shfl_xor_sync(0xFFFFFFFFu, bm0, off);
                    float ov1 = __shfl_xor_sync(0xFFFFFFFFu, bv1, off);
                    int   om1 = __shfl_xor_sync(0xFFFFFFFFu, bm1, off);
                    if (ov0 > bv0 || (ov0 == bv0 && om0 < bm0)) { bv0 = ov0; bm0 = om0; }
                    if (ov1 > bv1 || (ov1 == bv1 && om1 < bm1)) { bv1 = ov1; bm1 = om1; }
                }
                tv[0][t] = bv0; tm[0][t] = bm0;
                tv[1][t] = bv1; tm[1][t] = bm1;
                if ((bm0 & 31) == lane) u0 |= 1u << (bm0 >> 5);
                if ((bm1 & 31) == lane) u1 |= 1u << (bm1 >> 5);
            }
            #pragma unroll
            for (int s2 = 0; s2 < 2; s2++) {
                int ii = ip*2 + s2;
                float ww[8], wsum = 0.f;
                #pragma unroll
                for (int t = 0; t < 8; t++) { ww[t] = expf(tv[s2][t] - tv[s2][0]); wsum += ww[t]; }
                float winv = one_a/wsum;
                float fs[8] = {};
                #pragma unroll
                for (int t = 0; t < 8; t++) {
                    float att = ww[t]*winv;
                    int gidx = s_pool[tm[s2][t]];
                    const float* fvrow = g_fvT + (b*N_ + gidx)*C_;
                    #pragma unroll
                    for (int j = 0; j < 8; j++) fs[j] += att * fvrow[j*32 + lane];
                }
                #pragma unroll
                for (int j = 0; j < 8; j++) cb[ii][j] = fs[j];
            }
        }

        float lg[4] = {0.f, 0.f, 0.f, 0.f};
        #pragma unroll
        for (int dh = 0; dh < 2; dh++) {
            #pragma unroll 4
            for (int dd = 0; dd < 32; dd++) {
                float rkv = s_rk[lane*65 + dh*32 + dd];
                #pragma unroll
                for (int i = 0; i < 4; i++) {
                    float qd = __shfl_sync(0xFFFFFFFFu, dh ? q1[i] : q0[i], dd);
                    lg[i] += qd * rkv;
                }
            }
        }
        float mx[4], es[4], aat[4];
        #pragma unroll
        for (int i = 0; i < 4; i++) { lg[i] *= INVSCALE; mx[i] = lg[i]; }
        #pragma unroll
        for (int off = 16; off > 0; off >>= 1) {
            #pragma unroll
            for (int i = 0; i < 4; i++)
                mx[i] = fmaxf(mx[i], __shfl_xor_sync(0xFFFFFFFFu, mx[i], off));
        }
        #pragma unroll
        for (int i = 0; i < 4; i++) { aat[i] = expf(lg[i] - mx[i]); es[i] = aat[i]; }
        #pragma unroll
        for (int off = 16; off > 0; off >>= 1) {
            #pragma unroll
            for (int i = 0; i < 4; i++)
                es[i] += __shfl_xor_sync(0xFFFFFFFFu, es[i], off);
        }
        #pragma unroll
        for (int i = 0; i < 4; i++) aat[i] = a*aat[i]/es[i];

        #pragma unroll 4
        for (int kk = 0; kk < K_; kk++) {
            const float* rrow = s_rfv + kk*256;
            float r8[8];
            #pragma unroll
            for (int j = 0; j < 8; j++) r8[j] = rrow[j*32 + lane];
            #pragma unroll
            for (int i = 0; i < 4; i++) {
                float ak = __shfl_sync(0xFFFFFFFFu, aat[i], kk);
                #pragma unroll
                for (int j = 0; j < 8; j++) cb[i][j] += ak * r8[j];
            }
        }

        #pragma unroll 1
        for (int i = 0; i < 4; i++) {
            if (i >= nv) break;
            float pre[8], sum = 0.f, sq = 0.f;
            const float* xrow = g_xT + (b*N_+n[i])*C_;
            #pragma unroll
            for (int j = 0; j < 8; j++) {
                int c = j*32 + lane;
                float v = xrow[c] + cb[i][j] + fuse_b[c];
                pre[j] = v; sum += v; sq += v*v;
            }
            #pragma unroll
            for (int off = 16; off > 0; off >>= 1) {
                sum += __shfl_xor_sync(0xFFFFFFFFu, sum, off);
                sq  += __shfl_xor_sync(0xFFFFFFFFu, sq,  off);
            }
            float mu = sum * (1.f/256.f);
            float var = sq * (1.f/256.f) - mu*mu;
            float rstd = rsqrtf(var + 1e-5f);
            float* orow = g_outT + (b*N_+n[i])*C_;
            #pragma unroll
            for (int j = 0; j < 8; j++) {
                int c = j*32 + lane;
                orow[c] = (pre[j]-mu)*rstd*ln_g[c] + ln_b[c];
            }
        }
    }
}

// ----------------------------- launch -----------------------------
extern "C" void kernel_launch(void* const* d_in, const int* in_sizes, int n_in,
                              void* d_out, int out_size) {
    const float* x      = (const float*)d_in[0];
    const float* sem_w  = (const float*)d_in[1];
    const float* sem_b  = (const float*)d_in[2];
    const float* q_w    = (const float*)d_in[3];
    const float* k_w    = (const float*)d_in[4];
    const float* v_w    = (const float*)d_in[5];
    const float* fuse_w = (const float*)d_in[6];
    const float* fuse_b = (const float*)d_in[7];
    const float* alpha  = (const float*)d_in[8];
    const float* ln_g   = (const float*)d_in[9];
    const float* ln_b   = (const float*)d_in[10];
    float* out = (float*)d_out;

    const int SMEM_MAIN = (64*257 + 32*256 + 32*65)*4 + 256*4;
    cudaFuncSetAttribute((const void*)k_main,
                         cudaFuncAttributeMaxDynamicSharedMemorySize, SMEM_MAIN);
    cudaFuncSetAttribute((const void*)k_gemm,
                         cudaFuncAttributeMaxDynamicSharedMemorySize, GEMM_SMEM);

    k_pre<<<1114, 256>>>(x, sem_w, sem_b, q_w, k_w, v_w, fuse_w); // #1
    k_gemm<<<dim3(32, 4, B_), 256, GEMM_SMEM>>>();                // #2 (sem fused)
    k_regsel<<<224, 512>>>();                                     // #3 (region+sel fused)
    k_main<<<dim3(MCH, K_, B_), 256, SMEM_MAIN>>>(alpha, fuse_b, ln_g, ln_b); // #4 <- ncu slot
    k_transpO<<<dim3(8, 128, B_), dim3(32, 8)>>>(out);            // #5
}

// round 16
// speedup vs baseline: 1.4190x; 1.0319x over previous
#include <cuda_runtime.h>
#include <cuda_bf16.h>
#include <math.h>

#define B_ 2
#define C_ 256
#define N_ 4096
#define D_ 64
#define K_ 32
#define M_ 256
#define R_ 416
#define RP2 512
#define INVSCALE (1.0f/8.000001f)
typedef unsigned long long ull;
typedef unsigned int uint;

// ----------------------------- scratch -----------------------------
__device__ __align__(16) __nv_bfloat16 g_Wh[RP2*C_];
__device__ __align__(16) __nv_bfloat16 g_Wl[RP2*C_];
__device__ __align__(16) __nv_bfloat16 g_xh[B_*C_*N_];
__device__ __align__(16) __nv_bfloat16 g_xl[B_*C_*N_];
__device__ float g_bias[R_];
__device__ float g_P[B_*R_*N_];        // rows 96..415 used: [k(64); fv(256)]
__device__ float g_sem[B_*K_*N_];
__device__ int   g_ti[B_*K_*M_];
__device__ int   g_cnt[B_*K_];
__device__ int   g_plist[B_*K_*N_];
__device__ float g_qT[B_*N_*D_];
__device__ float g_kT[B_*N_*D_];
__device__ float g_fvT[B_*N_*C_];
__device__ float g_xT[B_*N_*C_];
__device__ float g_RK[B_*K_*D_];
__device__ float g_RFV[B_*K_*C_];
__device__ float g_outT[B_*N_*C_];

__device__ __forceinline__ void split_bf16(float v, __nv_bfloat16& h, __nv_bfloat16& l) {
    h = __float2bfloat16_rn(v);
    l = __float2bfloat16_rn(v - __bfloat162float(h));
}
__device__ __forceinline__ uint cvta_smem(const void* p) {
    return (uint)__cvta_generic_to_shared(p);
}
__device__ __forceinline__ uint fordk(float v) {
    uint u = __float_as_uint(v);
    return (u & 0x80000000u) ? ~u : (u | 0x80000000u);
}
__device__ __forceinline__ float iordk(uint k) {
    return __uint_as_float((k & 0x80000000u) ? (k & 0x7FFFFFFFu) : ~k);
}

// ----------------------------- k_pre (fused zero + cvtx + prep) -----------------------------
__global__ void __launch_bounds__(256) k_pre(
    const float* __restrict__ x,
    const float* __restrict__ sem_w, const float* __restrict__ sem_b,
    const float* __restrict__ q_w,  const float* __restrict__ k_w,
    const float* __restrict__ v_w,  const float* __restrict__ fuse_w) {
    int bx = blockIdx.x, tid = threadIdx.x;
    if (bx < 1024) {
        __shared__ float t[64][33];
        int n0 = (bx & 63)*64, c0 = ((bx >> 6) & 7)*32, b = bx >> 9;
        int tx = tid & 31, ty = tid >> 5;
        #pragma unroll
        for (int i = 0; i < 4; i++) {
            int c = c0 + ty + i*8;
            int n = n0 + tx*2;
            float2 v = *(const float2*)&x[(b*C_ + c)*N_ + n];
            __nv_bfloat16 h0, l0, h1, l1;
            split_bf16(v.x, h0, l0); split_bf16(v.y, h1, l1);
            uint hw = (uint)__bfloat16_as_ushort(h0) | ((uint)__bfloat16_as_ushort(h1) << 16);
            uint lw = (uint)__bfloat16_as_ushort(l0) | ((uint)__bfloat16_as_ushort(l1) << 16);
            *(uint*)&g_xh[(b*C_ + c)*N_ + n] = hw;
            *(uint*)&g_xl[(b*C_ + c)*N_ + n] = lw;
            t[tx*2][ty + i*8]     = v.x;
            t[tx*2 + 1][ty + i*8] = v.y;
        }
        __syncthreads();
        #pragma unroll
        for (int i = 0; i < 8; i++) {
            int nn = ty + i*8;
            g_xT[(b*N_ + n0 + nn)*C_ + c0 + tx] = t[nn][tx];
        }
    } else if (bx < 1066) {
        int blk = bx - 1024;
        if (blk < 10) {
            #pragma unroll
            for (int it = 0; it < 16; it++) {
                int e = tid + it*256;
                int r = blk*16 + (e >> 8), c = e & 255;
                float val = (r < 32) ? sem_w[r*C_ + c]
                          : (r < 96) ? q_w[(r-32)*C_ + c]
                                     : k_w[(r-96)*C_ + c];
                __nv_bfloat16 h, l; split_bf16(val, h, l);
                g_Wh[r*C_ + c] = h; g_Wl[r*C_ + c] = l;
                if (c == 0) g_bias[r] = (r < 32) ? sem_b[r] : 0.f;
            }
        } else {
            int r0 = 160 + (blk-10)*8;
            __shared__ float fw[8*256];
            #pragma unroll
            for (int it = 0; it < 8; it++) {
                int e = tid + it*256;
                fw[e] = fuse_w[(r0-160)*C_ + e];
            }
            __syncthreads();
            float acc[8] = {};
            for (int m = 0; m < C_; m++) {
                float v = v_w[m*C_ + tid];
                #pragma unroll
                for (int rr = 0; rr < 8; rr++) acc[rr] += fw[rr*256 + m] * v;
            }
            #pragma unroll
            for (int rr = 0; rr < 8; rr++) {
                int r = r0 + rr;
                __nv_bfloat16 h, l; split_bf16(acc[rr], h, l);
                g_Wh[r*C_ + tid] = h; g_Wl[r*C_ + tid] = l;
                if (tid == 0) g_bias[r] = 0.f;
            }
        }
    } else {
        int w = (bx - 1066)*256 + tid;
        ((uint*)g_Wh)[53248 + w] = 0;
        ((uint*)g_Wl)[53248 + w] = 0;
        if (w < 4096) ((float*)g_RK)[w] = 0.f;
        if (w < 8192) { g_RFV[w] = 0.f; g_RFV[w + 8192] = 0.f; }
        if (w < B_*K_) g_cnt[w] = 0;
    }
}

// ----------------------------- k_gemm (3-stage cp.async + ldmatrix; fused transpose + sem epilogue) ---
__device__ __forceinline__ void mma16816(float* d, const uint* a, uint b0, uint b1) {
    asm volatile(
        "mma.sync.aligned.m16n8k16.row.col.f32.bf16.bf16.f32 "
        "{%0,%1,%2,%3}, {%4,%5,%6,%7}, {%8,%9}, {%0,%1,%2,%3};"
        : "+f"(d[0]), "+f"(d[1]), "+f"(d[2]), "+f"(d[3])
        : "r"(a[0]), "r"(a[1]), "r"(a[2]), "r"(a[3]), "r"(b0), "r"(b1));
}
__device__ __forceinline__ void ldsm4(uint* r, uint addr) {
    asm volatile("ldmatrix.sync.aligned.m8n8.x4.shared.b16 {%0,%1,%2,%3}, [%4];"
        : "=r"(r[0]), "=r"(r[1]), "=r"(r[2]), "=r"(r[3]) : "r"(addr));
}
__device__ __forceinline__ void ldsm4t(uint* r, uint addr) {
    asm volatile("ldmatrix.sync.aligned.m8n8.x4.trans.shared.b16 {%0,%1,%2,%3}, [%4];"
        : "=r"(r[0]), "=r"(r[1]), "=r"(r[2]), "=r"(r[3]) : "r"(addr));
}
__device__ __forceinline__ void cpa16(uint dst, const void* src) {
    asm volatile("cp.async.cg.shared.global [%0], [%1], 16;" :: "r"(dst), "l"(src));
}

#define A_ST_BYTES (128*40*2)
#define B_ST_BYTES (32*136*2)
#define SB_BASE_OFF (6*A_ST_BYTES)
#define GEMM_SMEM (6*A_ST_BYTES + 6*B_ST_BYTES)

__device__ __forceinline__ void gemm_load(int st, int kc, int r0, int n0,
                                          const __nv_bfloat16* xh, const __nv_bfloat16* xl,
                                          uint sa_base, uint sb_base, int tid) {
    #pragma unroll
    for (int i = 0; i < 4; i++) {
        int ch = tid + i*256;
        int hl = ch >> 9, rem = ch & 511;
        int r = rem >> 2, c = (rem & 3)*8;
        const __nv_bfloat16* src = (hl ? g_Wl : g_Wh) + (r0 + r)*C_ + kc + c;
        cpa16(sa_base + (st*2 + hl)*A_ST_BYTES + (r*40 + c)*2, src);
    }
    #pragma unroll
    for (int i = 0; i < 4; i++) {
        int ch = tid + i*256;
        int hl = ch >> 9, rem = ch & 511;
        int k = rem >> 4, c = (rem & 15)*8;
        const __nv_bfloat16* src = (hl ? xl : xh) + (kc + k)*N_ + n0 + c;
        cpa16(sb_base + (st*2 + hl)*B_ST_BYTES + (k*136 + c)*2, src);
    }
    asm volatile("cp.async.commit_group;" ::: "memory");
}

__global__ void __launch_bounds__(256) k_gemm() {
    extern __shared__ __align__(16) char dsm[];
    uint sa_base = cvta_smem(dsm);
    uint sb_base = sa_base + SB_BASE_OFF;

    int n0 = blockIdx.x*128, r0 = blockIdx.y*128, b = blockIdx.z;
    int tid = threadIdx.x, lane = tid & 31, wid = tid >> 5;
    int wm = wid & 3, wn = wid >> 2;
    const __nv_bfloat16* xh = g_xh + b*C_*N_;
    const __nv_bfloat16* xl = g_xl + b*C_*N_;

    float acc[2][8][4];
    #pragma unroll
    for (int mt = 0; mt < 2; mt++)
        #pragma unroll
        for (int nt = 0; nt < 8; nt++)
            #pragma unroll
            for (int i = 0; i < 4; i++) acc[mt][nt][i] = 0.f;

    gemm_load(0, 0,  r0, n0, xh, xl, sa_base, sb_base, tid);
    gemm_load(1, 32, r0, n0, xh, xl, sa_base, sb_base, tid);

    for (int kt = 0; kt < 8; kt++) {
        if (kt < 7) asm volatile("cp.async.wait_group 1;" ::: "memory");
        else        asm volatile("cp.async.wait_group 0;" ::: "memory");
        __syncthreads();
        int st = kt % 3;
        uint sa0 = sa_base + (st*2+0)*A_ST_BYTES;
        uint sa1 = sa_base + (st*2+1)*A_ST_BYTES;
        uint sb0 = sb_base + (st*2+0)*B_ST_BYTES;
        uint sb1 = sb_base + (st*2+1)*B_ST_BYTES;
        #pragma unroll
        for (int k16 = 0; k16 < 2; k16++) {
            uint ah0[4], ah1[4], al0[4], al1[4];
            int ra = wm*32 + (lane & 15);
            int kcol = k16*16 + (lane >> 4)*8;
            ldsm4(ah0, sa0 + (ra*40 + kcol)*2);
            ldsm4(ah1, sa0 + ((ra+16)*40 + kcol)*2);
            ldsm4(al0, sa1 + (ra*40 + kcol)*2);
            ldsm4(al1, sa1 + ((ra+16)*40 + kcol)*2);
            int krow = k16*16 + (lane & 15);
            #pragma unroll
            for (int np = 0; np < 4; np++) {
                int nc = wn*64 + np*16 + (lane >> 4)*8;
                uint bh[4], bl[4];
                ldsm4t(bh, sb0 + (krow*136 + nc)*2);
                ldsm4t(bl, sb1 + (krow*136 + nc)*2);
                mma16816(acc[0][np*2],   ah0, bh[0], bh[1]);
                mma16816(acc[1][np*2],   ah1, bh[0], bh[1]);
                mma16816(acc[0][np*2+1], ah0, bh[2], bh[3]);
                mma16816(acc[1][np*2+1], ah1, bh[2], bh[3]);
                mma16816(acc[0][np*2],   ah0, bl[0], bl[1]);
                mma16816(acc[1][np*2],   ah1, bl[0], bl[1]);
                mma16816(acc[0][np*2+1], ah0, bl[2], bl[3]);
                mma16816(acc[1][np*2+1], ah1, bl[2], bl[3]);
                mma16816(acc[0][np*2],   al0, bh[0], bh[1]);
                mma16816(acc[1][np*2],   al1, bh[0], bh[1]);
                mma16816(acc[0][np*2+1], al0, bh[2], bh[3]);
                mma16816(acc[1][np*2+1], al1, bh[2], bh[3]);
            }
        }
        __syncthreads();
        if (kt + 2 < 8)
            gemm_load((kt+2) % 3, (kt+2)*32, r0, n0, xh, xl, sa_base, sb_base, tid);
    }

    // ---- epilogue: bias, P writes (rows >= 96 only), SMEM transpose for qT/kT/fvT ----
    float* T = (float*)dsm;                 // 128 x 133 floats
    #pragma unroll
    for (int mt = 0; mt < 2; mt++) {
        int rl = wm*32 + mt*16 + (lane >> 2);
        int r = r0 + rl;
        float bi0 = (r < R_) ? g_bias[r] : 0.f;
        float bi1 = (r + 8 < R_) ? g_bias[r + 8] : 0.f;
        #pragma unroll
        for (int nt = 0; nt < 8; nt++) {
            int nl = wn*64 + nt*8 + (lane & 3)*2;
            float v0 = acc[mt][nt][0] + bi0, v1 = acc[mt][nt][1] + bi0;
            float v2 = acc[mt][nt][2] + bi1, v3 = acc[mt][nt][3] + bi1;
            T[rl*133 + nl] = v0; T[rl*133 + nl + 1] = v1;
            T[(rl+8)*133 + nl] = v2; T[(rl+8)*133 + nl + 1] = v3;
            if (r >= 96 && r < R_)
                *(float2*)&g_P[(b*R_ + r)*N_ + n0 + nl] = make_float2(v0, v1);
            if (r + 8 >= 96 && r + 8 < R_)
                *(float2*)&g_P[(b*R_ + r + 8)*N_ + n0 + nl] = make_float2(v2, v3);
        }
    }
    __syncthreads();
    for (int i = 0; i < 64; i++) {
        int e = tid + i*256;
        int rl = e & 127, nl = e >> 7;
        int r = r0 + rl;
        if (r >= 32 && r < R_) {
            float v = T[rl*133 + nl];
            int n = n0 + nl;
            if (r < 96)       g_qT[(b*N_ + n)*D_ + (r - 32)]  = v;
            else if (r < 160) g_kT[(b*N_ + n)*D_ + (r - 96)]  = v;
            else              g_fvT[(b*N_ + n)*C_ + (r - 160)] = v;
        }
    }

    // ---- fused k_sem: r0==0 blocks hold sem rows 0..31 in T ----
    if (r0 == 0 && tid < 128) {
        int n = n0 + tid;
        float l[K_];
        float mx = -INFINITY; int am = 0;
        #pragma unroll
        for (int k = 0; k < K_; k++) {
            l[k] = T[k*133 + tid];
            if (l[k] > mx) { mx = l[k]; am = k; }
        }
        float sum = 0.f;
        #pragma unroll
        for (int k = 0; k < K_; k++) { l[k] = expf(l[k] - mx); sum += l[k]; }
        float inv = 1.f/sum;
        #pragma unroll
        for (int k = 0; k < K_; k++) g_sem[(b*K_ + k)*N_ + n] = l[k]*inv;
        int slot = atomicAdd(&g_cnt[b*K_ + am], 1);
        g_plist[(b*K_+am)*N_ + slot] = n;
    }
}

// ----------------------------- k_regsel (fused region + sel; 512 threads) -----------------------------
__global__ void __launch_bounds__(512) k_regsel() {
    __shared__ __align__(16) char sbuf[36992];
    __shared__ int s_tc, s_cA, s_t, s_A, s_nw, s_nc;
    int blk = blockIdx.x, tid = threadIdx.x;

    if (blk < 160) {
        float* ss = (float*)sbuf;              // 32*68 floats
        float* ps = ss + 32*68;                // 64*68 floats
        int ct = blk % 5, sp = (blk/5) & 15, b = blk/80;
        int kk = tid & 31, cg = (tid >> 5) & 7, half = tid >> 8;
        int nnbase = half*32;
        float acc[8] = {};
        for (int nch = 0; nch < 4; nch++) {
            int nn0 = sp*256 + nch*64;
            #pragma unroll
            for (int i = 0; i < 4; i++) {
                int e = tid + i*512; int kr = e >> 6, nn = e & 63;
                ss[kr*68+nn] = g_sem[(b*K_+kr)*N_ + nn0 + nn];
            }
            #pragma unroll
            for (int i = 0; i < 8; i++) {
                int e = tid + i*512; int c = e >> 6, nn = e & 63;
                ps[c*68+nn] = g_P[(b*R_ + 96 + ct*64 + c)*N_ + nn0 + nn];
            }
            __syncthreads();
            #pragma unroll 4
            for (int nn = 0; nn < 32; nn += 4) {
                float4 sv = *(const float4*)&ss[kk*68 + nnbase + nn];
                #pragma unroll
                for (int j = 0; j < 8; j++) {
                    float4 pv = *(const float4*)&ps[(cg*8+j)*68 + nnbase + nn];
                    acc[j] += sv.x*pv.x;
                    acc[j] += sv.y*pv.y;
                    acc[j] += sv.z*pv.z;
                    acc[j] += sv.w*pv.w;
                }
            }
            __syncthreads();
        }
        #pragma unroll
        for (int j = 0; j < 8; j++) {
            int o = ct*64 + cg*8 + j;
            if (o < 64) atomicAdd(&g_RK[(b*K_+kk)*D_ + o], acc[j]);
            else        atomicAdd(&g_RFV[(b*K_+kk)*C_ + (o-64)], acc[j]);
        }
        return;
    }

    // ---- sel part ----
    ull* cand = (ull*)sbuf;
    ull* win  = cand + 4096;
    int* sufc = (int*)(win + 256);
    unsigned* hist = (unsigned*)cand;

    int bk = blk - 160; int b = bk >> 5, k = bk & 31;
    const float* row = g_sem + (b*K_ + k)*N_;

    for (int i = tid; i < 4096; i += 512) hist[i] = 0;
    __syncthreads();

    unsigned vb[8];
    #pragma unroll
    for (int j = 0; j < 8; j++) {
        vb[j] = __float_as_uint(row[tid + j*512]);
        atomicAdd(&hist[vb[j] >> 20], 1);
    }
    __syncthreads();

    if (tid < 256) {
        int cs = 0;
        #pragma unroll
        for (int h = 0; h < 16; h++) cs += hist[tid*16 + h];
        sufc[tid] = cs;
    }
    __syncthreads();
    #pragma unroll
    for (int st = 1; st < 256; st <<= 1) {
        int add = (tid < 256 && tid + st < 256) ? sufc[tid + st] : 0;
        __syncthreads();
        if (tid < 256) sufc[tid] += add;
        __syncthreads();
    }
    if (tid < 256) {
        int nxt = (tid < 255) ? sufc[tid + 1] : 0;
        if (sufc[tid] >= M_ && nxt < M_) { s_tc = tid; s_cA = nxt; }
    }
    if (tid == 0) { s_nw = 0; s_nc = 0; }
    __syncthreads();
    int tc = s_tc, cA = s_cA;
    if (tid < 16) {
        int sg = 0;
        for (int j = tid; j < 16; j++) sg += hist[tc*16 + j];
        int hi = hist[tc*16 + tid];
        if (cA + sg >= M_ && cA + sg - hi < M_) { s_t = tc*16 + tid; s_A = cA + sg - hi; }
    }
    __syncthreads();
    int t = s_t, A = s_A, s = M_ - A;
    __syncthreads();

    #pragma unroll
    for (int j = 0; j < 8; j++) {
        unsigned v = vb[j];
        int idx = tid + j*512;
        unsigned bkt = v >> 20;
        ull key = ((ull)v << 32) | (unsigned)(0xFFFFFFFFu - (unsigned)idx);
        if ((int)bkt > t) { int p = atomicAdd(&s_nw, 1); win[p] = ~key; }
        else if ((int)bkt == t) { int p = atomicAdd(&s_nc, 1); cand[p] = ~key; }
    }
    __syncthreads();

    int nc = s_nc;
    int P = 1; while (P < nc) P <<= 1;
    for (int i = tid; i < P; i += 512) if (i >= nc) cand[i] = 0xFFFFFFFFFFFFFFFFULL;
    __syncthreads();
    for (int sz = 2; sz <= P; sz <<= 1) {
        for (int str = sz >> 1; str > 0; str >>= 1) {
            for (int i = tid; i < P; i += 512) {
                int l = i ^ str;
                if (l > i) {
                    ull a = cand[i], c2 = cand[l];
                    bool up = ((i & sz) == 0);
                    if ((a > c2) == up) { cand[i] = c2; cand[l] = a; }
                }
            }
            __syncthreads();
        }
    }
    for (int i = tid; i < s; i += 512) win[A + i] = cand[i];
    __syncthreads();
    for (int sz = 2; sz <= 256; sz <<= 1) {
        for (int str = sz >> 1; str > 0; str >>= 1) {
            if (tid < 256) {
                int i = tid, l = i ^ str;
                if (l > i) {
                    ull a = win[i], c2 = win[l];
                    bool up = ((i & sz) == 0);
                    if ((a > c2) == up) { win[i] = c2; win[l] = a; }
                }
            }
            __syncthreads();
        }
    }
    if (tid < 256) g_ti[(b*K_ + k)*M_ + tid] = (int)(unsigned)(win[tid] & 0xFFFFFFFFu);
}

// ----------------------------- k_transpO -----------------------------
__global__ void k_transpO(float* __restrict__ out) {
    __shared__ float t[32][33];
    int b = blockIdx.z, c0 = blockIdx.x*32, n0 = blockIdx.y*32;
    int tx = threadIdx.x, ty = threadIdx.y;
    #pragma unroll
    for (int i = 0; i < 32; i += 8)
        t[ty+i][tx] = g_outT[b*N_*C_ + (n0 + ty + i)*C_ + c0 + tx];
    __syncthreads();
    #pragma unroll
    for (int i = 0; i < 32; i += 8)
        out[b*C_*N_ + (c0 + ty + i)*N_ + n0 + tx] = t[tx][ty+i];
}

// ----------------------------- k_main (redux top-8, float2 channels) -----------------------------
#define MCH 32
__global__ void __launch_bounds__(256) k_main(const float* __restrict__ alpha_p,
                                              const float* __restrict__ fuse_b,
                                              const float* __restrict__ ln_g,
                                              const float* __restrict__ ln_b) {
    extern __shared__ float sm[];
    float* s_pkT = sm;                         // 64*257
    float* s_rfv = s_pkT + 64*257;             // 32*256
    float* s_rk  = s_rfv + 32*256;             // 32*65
    int*   s_pool= (int*)(s_rk + 32*65);       // 256

    int reg = blockIdx.y, b = blockIdx.z;
    int cnt = g_cnt[b*K_ + reg];
    if ((int)blockIdx.x * 32 >= cnt) return;
    int tid = threadIdx.x, lane = tid & 31, w = tid >> 5;

    if (tid < M_) s_pool[tid] = g_ti[(b*K_+reg)*M_ + tid];
    __syncthreads();
    #pragma unroll 4
    for (int i = 0; i < 64; i++) {
        int e = tid + i*256;
        int m = e >> 6, d = e & 63;
        s_pkT[d*257 + m] = g_kT[(b*N_ + s_pool[m])*D_ + d];
    }
    #pragma unroll
    for (int i = 0; i < 32; i++) s_rfv[tid + i*256] = g_RFV[b*K_*C_ + tid + i*256];
    #pragma unroll
    for (int i = 0; i < 8; i++) {
        int e = tid + i*256; int kk = e >> 6, d = e & 63;
        s_rk[kk*65+d] = g_RK[(b*K_+kk)*D_ + d];
    }
    __syncthreads();

    float a = 1.f/(1.f + expf(-alpha_p[0]));
    float one_a = 1.f - a;

    for (int chunk = blockIdx.x; chunk*32 < cnt; chunk += MCH) {
        int base = chunk*32;
        int pend = min(base+32, cnt);
        int p0 = base + w*4;
        if (p0 >= pend) continue;
        int nv = min(4, pend - p0);
        int n[4]; float q0[4], q1[4];
        #pragma unroll
        for (int i = 0; i < 4; i++) {
            if (i < nv) {
                n[i] = g_plist[(b*K_+reg)*N_ + p0 + i];
                q0[i] = g_qT[(b*N_+n[i])*D_ + lane];
                q1[i] = g_qT[(b*N_+n[i])*D_ + 32 + lane];
            } else { n[i] = 0; q0[i] = 0.f; q1[i] = 0.f; }
        }

        float sims[4][8] = {};
        #pragma unroll
        for (int dh = 0; dh < 2; dh++) {
            #pragma unroll 2
            for (int dd = 0; dd < 32; dd++) {
                const float* rowp = s_pkT + (dh*32+dd)*257;
                float r8[8];
                #pragma unroll
                for (int mi = 0; mi < 8; mi++) r8[mi] = rowp[mi*32 + lane];
                #pragma unroll
                for (int i = 0; i < 4; i++) {
                    float qd = __shfl_sync(0xFFFFFFFFu, dh ? q1[i] : q0[i], dd);
                    #pragma unroll
                    for (int mi = 0; mi < 8; mi++) sims[i][mi] += qd * r8[mi];
                }
            }
        }
        #pragma unroll
        for (int i = 0; i < 4; i++)
            #pragma unroll
            for (int mi = 0; mi < 8; mi++) sims[i][mi] *= INVSCALE;

        // pairwise top-8 via REDUX + softmax + float2 sparse gather
        float cb[4][8];
        #pragma unroll
        for (int ip = 0; ip < 2; ip++) {
            int i0 = ip*2, i1 = ip*2 + 1;
            float tv[2][8]; int tm[2][8];
            unsigned u0 = 0, u1 = 0;
            #pragma unroll
            for (int t = 0; t < 8; t++) {
                float bv0 = -INFINITY, bv1 = -INFINITY;
                int bm0 = 1 << 30, bm1 = 1 << 30;
                #pragma unroll
                for (int mi = 0; mi < 8; mi++) {
                    int m = mi*32 + lane;
                    if (!(u0 & (1u << mi))) {
                        float v = sims[i0][mi];
                        if (v > bv0 || (v == bv0 && m < bm0)) { bv0 = v; bm0 = m; }
                    }
                    if (!(u1 & (1u << mi))) {
                        float v = sims[i1][mi];
                        if (v > bv1 || (v == bv1 && m < bm1)) { bv1 = v; bm1 = m; }
                    }
                }
                uint k0 = fordk(bv0), k1 = fordk(bv1);
                uint mx0 = __reduce_max_sync(0xFFFFFFFFu, k0);
                uint mx1 = __reduce_max_sync(0xFFFFFFFFu, k1);
                int c0 = (k0 == mx0) ? bm0 : (1 << 30);
                int c1 = (k1 == mx1) ? bm1 : (1 << 30);
                int w0 = __reduce_min_sync(0xFFFFFFFFu, c0);
                int w1 = __reduce_min_sync(0xFFFFFFFFu, c1);
                tv[0][t] = iordk(mx0); tm[0][t] = w0;
                tv[1][t] = iordk(mx1); tm[1][t] = w1;
                if ((w0 & 31) == lane) u0 |= 1u << (w0 >> 5);
                if ((w1 & 31) == lane) u1 |= 1u << (w1 >> 5);
            }
            #pragma unroll
            for (int s2 = 0; s2 < 2; s2++) {
                int ii = ip*2 + s2;
                float ww[8], wsum = 0.f;
                #pragma unroll
                for (int t = 0; t < 8; t++) { ww[t] = expf(tv[s2][t] - tv[s2][0]); wsum += ww[t]; }
                float winv = one_a/wsum;
                float2 fs[4] = {{0.f,0.f},{0.f,0.f},{0.f,0.f},{0.f,0.f}};
                #pragma unroll
                for (int t = 0; t < 8; t++) {
                    float att = ww[t]*winv;
                    int gidx = s_pool[tm[s2][t]];
                    const float2* fvrow = (const float2*)(g_fvT + (b*N_ + gidx)*C_);
                    #pragma unroll
                    for (int cj = 0; cj < 4; cj++) {
                        float2 fv = fvrow[cj*32 + lane];
                        fs[cj].x += att * fv.x;
                        fs[cj].y += att * fv.y;
                    }
                }
                #pragma unroll
                for (int cj = 0; cj < 4; cj++) {
                    cb[ii][cj*2]   = fs[cj].x;
                    cb[ii][cj*2+1] = fs[cj].y;
                }
            }
        }

        // batched dense logits: lg[i][k=lane] = q_i . rk[lane]
        float lg[4] = {0.f, 0.f, 0.f, 0.f};
        #pragma unroll
        for (int dh = 0; dh < 2; dh++) {
            #pragma unroll 4
            for (int dd = 0; dd < 32; dd++) {
                float rkv = s_rk[lane*65 + dh*32 + dd];
                #pragma unroll
                for (int i = 0; i < 4; i++) {
                    float qd = __shfl_sync(0xFFFFFFFFu, dh ? q1[i] : q0[i], dd);
                    lg[i] += qd * rkv;
                }
            }
        }
        float mx[4], es[4], aat[4];
        #pragma unroll
        for (int i = 0; i < 4; i++) { lg[i] *= INVSCALE; mx[i] = lg[i]; }
        #pragma unroll
        for (int off = 16; off > 0; off >>= 1) {
            #pragma unroll
            for (int i = 0; i < 4; i++)
                mx[i] = fmaxf(mx[i], __shfl_xor_sync(0xFFFFFFFFu, mx[i], off));
        }
        #pragma unroll
        for (int i = 0; i < 4; i++) { aat[i] = expf(lg[i] - mx[i]); es[i] = aat[i]; }
        #pragma unroll
        for (int off = 16; off > 0; off >>= 1) {
            #pragma unroll
            for (int i = 0; i < 4; i++)
                es[i] += __shfl_xor_sync(0xFFFFFFFFu, es[i], off);
        }
        #pragma unroll
        for (int i = 0; i < 4; i++) aat[i] = a*aat[i]/es[i];

        // batched fc accumulate into cb (float2 LDS)
        #pragma unroll 4
        for (int kk = 0; kk < K_; kk++) {
            const float2* rrow = (const float2*)(s_rfv + kk*256);
            float2 r4[4];
            #pragma unroll
            for (int cj = 0; cj < 4; cj++) r4[cj] = rrow[cj*32 + lane];
            #pragma unroll
            for (int i = 0; i < 4; i++) {
                float ak = __shfl_sync(0xFFFFFFFFu, aat[i], kk);
                #pragma unroll
                for (int cj = 0; cj < 4; cj++) {
                    cb[i][cj*2]   += ak * r4[cj].x;
                    cb[i][cj*2+1] += ak * r4[cj].y;
                }
            }
        }

        // per-position epilogue: bias + residual + channel LN (float2 channels)
        const float2* fb2 = (const float2*)fuse_b;
        const float2* lg2 = (const float2*)ln_g;
        const float2* lb2 = (const float2*)ln_b;
        #pragma unroll 1
        for (int i = 0; i < 4; i++) {
            if (i >= nv) break;
            float2 pre[4]; float sum = 0.f, sq = 0.f;
            const float2* xrow = (const float2*)(g_xT + (b*N_+n[i])*C_);
            #pragma unroll
            for (int cj = 0; cj < 4; cj++) {
                float2 xv = xrow[cj*32 + lane];
                float2 fb = fb2[cj*32 + lane];
                float vx = xv.x + cb[i][cj*2]   + fb.x;
                float vy = xv.y + cb[i][cj*2+1] + fb.y;
                pre[cj].x = vx; pre[cj].y = vy;
                sum += vx + vy; sq += vx*vx + vy*vy;
            }
            #pragma unroll
            for (int off = 16; off > 0; off >>= 1) {
                sum += __shfl_xor_sync(0xFFFFFFFFu, sum, off);
                sq  += __shfl_xor_sync(0xFFFFFFFFu, sq,  off);
            }
            float mu = sum * (1.f/256.f);
            float var = sq * (1.f/256.f) - mu*mu;
            float rstd = rsqrtf(var + 1e-5f);
            float2* orow = (float2*)(g_outT + (b*N_+n[i])*C_);
            #pragma unroll
            for (int cj = 0; cj < 4; cj++) {
                float2 gg = lg2[cj*32 + lane];
                float2 bb = lb2[cj*32 + lane];
                float2 o;
                o.x = (pre[cj].x - mu)*rstd*gg.x + bb.x;
                o.y = (pre[cj].y - mu)*rstd*gg.y + bb.y;
                orow[cj*32 + lane] = o;
            }
        }
    }
}

// ----------------------------- launch -----------------------------
extern "C" void kernel_launch(void* const* d_in, const int* in_sizes, int n_in,
                              void* d_out, int out_size) {
    const float* x      = (const float*)d_in[0];
    const float* sem_w  = (const float*)d_in[1];
    const float* sem_b  = (const float*)d_in[2];
    const float* q_w    = (const float*)d_in[3];
    const float* k_w    = (const float*)d_in[4];
    const float* v_w    = (const float*)d_in[5];
    const float* fuse_w = (const float*)d_in[6];
    const float* fuse_b = (const float*)d_in[7];
    const float* alpha  = (const float*)d_in[8];
    const float* ln_g   = (const float*)d_in[9];
    const float* ln_b   = (const float*)d_in[10];
    float* out = (float*)d_out;

    const int SMEM_MAIN = (64*257 + 32*256 + 32*65)*4 + 256*4;
    cudaFuncSetAttribute((const void*)k_main,
                         cudaFuncAttributeMaxDynamicSharedMemorySize, SMEM_MAIN);
    cudaFuncSetAttribute((const void*)k_gemm,
                         cudaFuncAttributeMaxDynamicSharedMemorySize, GEMM_SMEM);

    k_pre<<<1114, 256>>>(x, sem_w, sem_b, q_w, k_w, v_w, fuse_w); // #1
    k_gemm<<<dim3(32, 4, B_), 256, GEMM_SMEM>>>();                // #2 (sem fused)
    k_regsel<<<224, 512>>>();                                     // #3 (region+sel fused)
    k_main<<<dim3(MCH, K_, B_), 256, SMEM_MAIN>>>(alpha, fuse_b, ln_g, ln_b); // #4 <- ncu slot
    k_transpO<<<dim3(8, 128, B_), dim3(32, 8)>>>(out);            // #5
}